// round 1
// baseline (speedup 1.0000x reference)
#include <cuda_runtime.h>
#include <math.h>

// Problem constants
#define B_   2
#define S_   2048
#define DM   1024
#define H_   16
#define DK   64
#define MTOT (B_ * S_)   // 4096
#define NEG_BIG (-3.402823466e38f)

// Scratch (device globals — allowed; no runtime allocation)
__device__ float g_q[B_ * H_ * S_ * DK];     // [B,H,S,DK]
__device__ float g_k[B_ * H_ * S_ * DK];
__device__ float g_v[B_ * H_ * S_ * DK];
__device__ float g_att[MTOT * DM];           // [B*S, DM]

// ---------------------------------------------------------------------------
// GEMM (NT): C[m,n] = sum_k A[m,k] * W[n,k] + bias[n]
// A: [4096,1024] row-major, W: [1024,1024] row-major.
// mode 0: write permuted into [B,H,S,DK] (for Q/K/V)
// mode 1: write plain [M,N] (final output)
// 128x128 tile, BK=8, 256 threads, 8x8 per thread.
// ---------------------------------------------------------------------------
__global__ void __launch_bounds__(256) gemm_nt_kernel(
    const float* __restrict__ A, const float* __restrict__ W,
    const float* __restrict__ bias, float* __restrict__ C, int mode)
{
    __shared__ float As[8][128];
    __shared__ float Ws[8][128];

    const int tid = threadIdx.x;
    const int tx = tid & 15;       // 0..15 (n direction)
    const int ty = tid >> 4;       // 0..15 (m direction)
    const int m0 = blockIdx.y * 128;
    const int n0 = blockIdx.x * 128;

    const int lrow = tid >> 1;         // 0..127
    const int lk   = (tid & 1) * 4;    // 0 or 4

    const float* Aptr = A + (size_t)(m0 + lrow) * 1024 + lk;
    const float* Wptr = W + (size_t)(n0 + lrow) * 1024 + lk;

    float acc[8][8];
    #pragma unroll
    for (int i = 0; i < 8; i++)
        #pragma unroll
        for (int j = 0; j < 8; j++) acc[i][j] = 0.f;

    for (int k0 = 0; k0 < 1024; k0 += 8) {
        float4 av = *(const float4*)(Aptr + k0);
        float4 wv = *(const float4*)(Wptr + k0);
        As[lk + 0][lrow] = av.x; As[lk + 1][lrow] = av.y;
        As[lk + 2][lrow] = av.z; As[lk + 3][lrow] = av.w;
        Ws[lk + 0][lrow] = wv.x; Ws[lk + 1][lrow] = wv.y;
        Ws[lk + 2][lrow] = wv.z; Ws[lk + 3][lrow] = wv.w;
        __syncthreads();

        #pragma unroll
        for (int kk = 0; kk < 8; kk++) {
            float a[8], b[8];
            #pragma unroll
            for (int i = 0; i < 8; i++) a[i] = As[kk][ty * 8 + i];
            #pragma unroll
            for (int j = 0; j < 8; j++) b[j] = Ws[kk][tx * 8 + j];
            #pragma unroll
            for (int i = 0; i < 8; i++)
                #pragma unroll
                for (int j = 0; j < 8; j++) acc[i][j] += a[i] * b[j];
        }
        __syncthreads();
    }

    #pragma unroll
    for (int i = 0; i < 8; i++) {
        const int m = m0 + ty * 8 + i;
        #pragma unroll
        for (int j = 0; j < 8; j++) {
            const int n = n0 + tx * 8 + j;
            float v = acc[i][j] + bias[n];
            if (mode == 0) {
                // m = b*S + s ; n = h*DK + d  ->  [B,H,S,DK]
                const int b = m >> 11;       // /2048
                const int s = m & 2047;
                const int h = n >> 6;        // /64
                const int d = n & 63;
                C[(((size_t)(b * H_ + h) * S_) + s) * DK + d] = v;
            } else {
                C[(size_t)m * DM + n] = v;
            }
        }
    }
}

// ---------------------------------------------------------------------------
// Flash attention (causal + attention_mask), fp32.
// Grid: (S/128, H, B). 128 threads; thread t owns query row q0+t.
// q[64] and acc[64] in registers; K/V tiles (64x64) in SMEM; online softmax
// over chunks of 32 keys (p[32] live).
// Writes attention output directly in [B,S,DM] layout for the final GEMM.
// ---------------------------------------------------------------------------
__global__ void __launch_bounds__(128) flash_attn_kernel(
    const float* __restrict__ Q, const float* __restrict__ K,
    const float* __restrict__ V, const int* __restrict__ amask,
    float* __restrict__ O)
{
    __shared__ float Ks[64][DK];   // 16 KB
    __shared__ float Vs[64][DK];   // 16 KB
    __shared__ int   mskv[64];

    const int b = blockIdx.z;
    const int h = blockIdx.y;
    const int q0 = blockIdx.x * 128;
    const int t = threadIdx.x;
    const int qrow = q0 + t;

    const size_t head_base = ((size_t)(b * H_ + h)) * S_ * DK;
    const float* qptr = Q + head_base + (size_t)qrow * DK;
    const float* kbase = K + head_base;
    const float* vbase = V + head_base;
    const int* mbase = amask + b * S_;

    float q[DK];
    #pragma unroll
    for (int d = 0; d < DK; d += 4) {
        float4 v = *(const float4*)(qptr + d);
        q[d] = v.x; q[d + 1] = v.y; q[d + 2] = v.z; q[d + 3] = v.w;
    }

    float acc[DK];
    #pragma unroll
    for (int d = 0; d < DK; d++) acc[d] = 0.f;
    float mrun = NEG_BIG, lrun = 0.f;

    const int kend = q0 + 128;   // exclusive; covers causal range for this tile

    for (int k0 = 0; k0 < kend; k0 += 64) {
        // cooperative tile load: 64x64 floats = 1024 float4, 8 per thread
        #pragma unroll
        for (int i = 0; i < 8; i++) {
            const int idx = t + i * 128;       // float4 index 0..1023
            const int r = idx >> 4;            // row 0..63
            const int c = (idx & 15) * 4;      // col
            *(float4*)&Ks[r][c] = *(const float4*)(kbase + (size_t)(k0 + r) * DK + c);
            *(float4*)&Vs[r][c] = *(const float4*)(vbase + (size_t)(k0 + r) * DK + c);
        }
        if (t < 64) mskv[t] = mbase[k0 + t];
        __syncthreads();

        #pragma unroll
        for (int half = 0; half < 2; half++) {
            const int kb = half * 32;
            if (k0 + kb > qrow) break;   // entire chunk above diagonal

            float p[32];
            float mloc = NEG_BIG;
            #pragma unroll
            for (int kk = 0; kk < 32; kk++) {
                const int kg = k0 + kb + kk;
                float s = 0.f;
                #pragma unroll
                for (int d = 0; d < DK; d++) s += q[d] * Ks[kb + kk][d];
                s *= 0.125f;   // 1/sqrt(64)
                const bool valid = (kg <= qrow) && (mskv[kb + kk] != 0);
                s = valid ? s : NEG_BIG;
                p[kk] = s;
                mloc = fmaxf(mloc, s);
            }
            const float mnew = fmaxf(mrun, mloc);
            const float corr = __expf(mrun - mnew);   // 1 when both NEG_BIG
            float lsum = 0.f;
            #pragma unroll
            for (int kk = 0; kk < 32; kk++) {
                const float e = (p[kk] == NEG_BIG) ? 0.f : __expf(p[kk] - mnew);
                p[kk] = e;
                lsum += e;
            }
            lrun = lrun * corr + lsum;
            #pragma unroll
            for (int d = 0; d < DK; d++) acc[d] *= corr;
            #pragma unroll
            for (int kk = 0; kk < 32; kk++) {
                const float pv = p[kk];
                #pragma unroll
                for (int d = 0; d < DK; d++) acc[d] += pv * Vs[kb + kk][d];
            }
            mrun = mnew;
        }
        __syncthreads();
    }

    const float inv = 1.f / lrun;
    float* optr = O + ((size_t)(b * S_) + qrow) * DM + h * DK;
    #pragma unroll
    for (int d = 0; d < DK; d += 4) {
        float4 v;
        v.x = acc[d] * inv; v.y = acc[d + 1] * inv;
        v.z = acc[d + 2] * inv; v.w = acc[d + 3] * inv;
        *(float4*)(optr + d) = v;
    }
}

// ---------------------------------------------------------------------------
// Launch
// Inputs (metadata order): x, attention_mask, w_q, b_q, w_k, b_k, w_v, b_v,
//                          w_o, b_o
// ---------------------------------------------------------------------------
extern "C" void kernel_launch(void* const* d_in, const int* in_sizes, int n_in,
                              void* d_out, int out_size)
{
    const float* x  = (const float*)d_in[0];
    const int*   am = (const int*)d_in[1];
    const float* wq = (const float*)d_in[2];
    const float* bq = (const float*)d_in[3];
    const float* wk = (const float*)d_in[4];
    const float* bk = (const float*)d_in[5];
    const float* wv = (const float*)d_in[6];
    const float* bv = (const float*)d_in[7];
    const float* wo = (const float*)d_in[8];
    const float* bo = (const float*)d_in[9];
    float* out = (float*)d_out;

    float *qp, *kp, *vp, *ap;
    cudaGetSymbolAddress((void**)&qp, g_q);
    cudaGetSymbolAddress((void**)&kp, g_k);
    cudaGetSymbolAddress((void**)&vp, g_v);
    cudaGetSymbolAddress((void**)&ap, g_att);

    dim3 ggrid(DM / 128, MTOT / 128);   // (8, 32)
    gemm_nt_kernel<<<ggrid, 256>>>(x, wq, bq, qp, 0);
    gemm_nt_kernel<<<ggrid, 256>>>(x, wk, bk, kp, 0);
    gemm_nt_kernel<<<ggrid, 256>>>(x, wv, bv, vp, 0);

    dim3 agrid(S_ / 128, H_, B_);       // (16, 16, 2)
    flash_attn_kernel<<<agrid, 128>>>(qp, kp, vp, am, ap);

    gemm_nt_kernel<<<ggrid, 256>>>(ap, wo, bo, out, 1);
}

// round 3
// speedup vs baseline: 1.5054x; 1.5054x over previous
#include <cuda_runtime.h>
#include <math.h>
#include <cstdint>

// Problem constants
#define B_   2
#define S_   2048
#define DM   1024
#define H_   16
#define DK   64
#define MTOT (B_ * S_)   // 4096
#define NEG_BIG (-3.402823466e38f)

// Scratch (device globals — allowed; no runtime allocation)
__device__ float g_q[B_ * H_ * S_ * DK];     // [B,H,S,DK]
__device__ float g_k[B_ * H_ * S_ * DK];
__device__ float g_v[B_ * H_ * S_ * DK];
__device__ float g_att[MTOT * DM];           // [B*S, DM]

__device__ __forceinline__ uint32_t smem_u32(const void* p) {
    uint32_t a;
    asm("{ .reg .u64 t; cvta.to.shared.u64 t, %1; cvt.u32.u64 %0, t; }"
        : "=r"(a) : "l"(p));
    return a;
}

#define CP_ASYNC16(dst, src) \
    asm volatile("cp.async.cg.shared.global [%0], [%1], 16;" :: "r"(dst), "l"(src))
#define CP_COMMIT() asm volatile("cp.async.commit_group;" ::: "memory")
#define CP_WAIT1()  asm volatile("cp.async.wait_group 1;" ::: "memory")

#define CVT_TF32(x) \
    asm volatile("cvt.rna.tf32.f32 %0, %1;" : "=r"(x) : "f"(__uint_as_float(x)))

#define LDSM_X4(r0, r1, r2, r3, addr) \
    asm volatile("ldmatrix.sync.aligned.m8n8.x4.shared.b16 {%0,%1,%2,%3}, [%4];" \
                 : "=r"(r0), "=r"(r1), "=r"(r2), "=r"(r3) : "r"(addr))

#define MMA_TF32(c, a, b) \
    asm volatile("mma.sync.aligned.m16n8k8.row.col.f32.tf32.tf32.f32 " \
                 "{%0,%1,%2,%3}, {%4,%5,%6,%7}, {%8,%9}, {%0,%1,%2,%3};" \
                 : "+f"((c)[0]), "+f"((c)[1]), "+f"((c)[2]), "+f"((c)[3]) \
                 : "r"((a)[0]), "r"((a)[1]), "r"((a)[2]), "r"((a)[3]), \
                   "r"((b)[0]), "r"((b)[1]))

// ===========================================================================
// Tensor-core tf32 GEMM (NT): C[m,n] = sum_k A[m,k] * W[n,k] + bias[n]
// A: [4096,1024] fp32 RM, W: [1024,1024] fp32 RM.
// Block 128x128, BK=32, 256 threads (8 warps, 2x4), warp tile 64x32.
// cp.async double-buffered; XOR-swizzled smem; ldmatrix + mma.sync tf32.
// mode 0: permuted write into [B,H,S,DK];  mode 1: plain [M,N].
// smem: A0[16K] B0[16K] A1[16K] B1[16K] = 64KB dynamic.
// ===========================================================================
__global__ void __launch_bounds__(256, 1) gemm_tc_kernel(
    const float* __restrict__ A, const float* __restrict__ W,
    const float* __restrict__ bias, float* __restrict__ C, int mode)
{
    extern __shared__ char smem[];
    const uint32_t sbase = smem_u32(smem);
    const int tid = threadIdx.x;
    const int lane = tid & 31;
    const int wid = tid >> 5;
    const int wm = wid >> 2;       // 0..1 (m)
    const int wn = wid & 3;        // 0..3 (n)
    const int m0 = blockIdx.y * 128;
    const int n0 = blockIdx.x * 128;

    // global->smem load mapping: 1024 16B-chunks per 128x32 tile, 4 per thread
    int lrow[4], lkg[4];
    uint32_t ldst[4];
    #pragma unroll
    for (int it = 0; it < 4; it++) {
        const int c = tid + it * 256;
        const int r = c >> 3, kg = c & 7;
        lrow[it] = r; lkg[it] = kg;
        ldst[it] = (uint32_t)(r * 128 + ((kg ^ (r & 7)) * 16));
    }

    // ldmatrix lane address components
    const int lrA = (lane & 7) + ((lane >> 3) & 1) * 8;  // 0..15 (row in m-tile)
    const int lkA = lane >> 4;                           // 0..1  (16B group)
    const int lrB = (lane & 7) + (lane >> 4) * 8;        // 0..15 (row in n-pair)
    const int lkB = (lane >> 3) & 1;

    float acc[4][4][4];
    #pragma unroll
    for (int i = 0; i < 4; i++)
        #pragma unroll
        for (int j = 0; j < 4; j++)
            #pragma unroll
            for (int r = 0; r < 4; r++) acc[i][j][r] = 0.f;

    auto load_tiles = [&](int buf, int k0) {
        const uint32_t ab = sbase + buf * 32768u;
        const uint32_t bb = ab + 16384u;
        #pragma unroll
        for (int it = 0; it < 4; it++) {
            const float* ga = A + (size_t)(m0 + lrow[it]) * 1024 + k0 + lkg[it] * 4;
            const float* gb = W + (size_t)(n0 + lrow[it]) * 1024 + k0 + lkg[it] * 4;
            CP_ASYNC16(ab + ldst[it], ga);
            CP_ASYNC16(bb + ldst[it], gb);
        }
    };

    auto compute = [&](int buf) {
        const uint32_t ab = sbase + buf * 32768u;
        const uint32_t bb = ab + 16384u;
        #pragma unroll
        for (int ks = 0; ks < 4; ks++) {
            uint32_t a[4][4];
            #pragma unroll
            for (int mt = 0; mt < 4; mt++) {
                const uint32_t addr = ab +
                    (uint32_t)((wm * 64 + mt * 16 + lrA) * 128 +
                               (((ks * 2 + lkA) ^ (lrA & 7)) * 16));
                LDSM_X4(a[mt][0], a[mt][1], a[mt][2], a[mt][3], addr);
            }
            uint32_t b[4][2];
            #pragma unroll
            for (int np = 0; np < 2; np++) {
                const uint32_t addr = bb +
                    (uint32_t)((wn * 32 + np * 16 + lrB) * 128 +
                               (((ks * 2 + lkB) ^ (lrB & 7)) * 16));
                LDSM_X4(b[np * 2][0], b[np * 2][1], b[np * 2 + 1][0], b[np * 2 + 1][1], addr);
            }
            #pragma unroll
            for (int mt = 0; mt < 4; mt++)
                #pragma unroll
                for (int j = 0; j < 4; j++) CVT_TF32(a[mt][j]);
            #pragma unroll
            for (int nt = 0; nt < 4; nt++) {
                CVT_TF32(b[nt][0]); CVT_TF32(b[nt][1]);
            }
            #pragma unroll
            for (int mt = 0; mt < 4; mt++)
                #pragma unroll
                for (int nt = 0; nt < 4; nt++)
                    MMA_TF32(acc[mt][nt], a[mt], b[nt]);
        }
    };

    load_tiles(0, 0);  CP_COMMIT();
    load_tiles(1, 32); CP_COMMIT();

    for (int i = 0; i < 32; i++) {
        CP_WAIT1();
        __syncthreads();
        compute(i & 1);
        __syncthreads();
        if (i + 2 < 32) load_tiles(i & 1, (i + 2) * 32);
        CP_COMMIT();
    }

    // Epilogue: c0,c1 at (r, 2c..2c+1); c2,c3 at (r+8, same cols)
    const int lr = lane >> 2;
    const int lc = (lane & 3) * 2;
    #pragma unroll
    for (int mt = 0; mt < 4; mt++) {
        const int m = m0 + wm * 64 + mt * 16 + lr;
        #pragma unroll
        for (int nt = 0; nt < 4; nt++) {
            const int n = n0 + wn * 32 + nt * 8 + lc;
            const float b0 = __ldg(bias + n);
            const float b1 = __ldg(bias + n + 1);
            float2 v0 = make_float2(acc[mt][nt][0] + b0, acc[mt][nt][1] + b1);
            float2 v1 = make_float2(acc[mt][nt][2] + b0, acc[mt][nt][3] + b1);
            if (mode == 0) {
                const int bb = m >> 11;
                const int s  = m & 2047;
                const int h  = n >> 6;
                const int d  = n & 63;
                float* p0 = C + (((size_t)(bb * H_ + h) * S_) + s) * DK + d;
                *(float2*)p0 = v0;
                *(float2*)(p0 + 8 * DK) = v1;   // row m+8: same b,h; s+8
            } else {
                float* p0 = C + (size_t)m * DM + n;
                *(float2*)p0 = v0;
                *(float2*)(p0 + 8 * DM) = v1;
            }
        }
    }
}

// ---------------------------------------------------------------------------
// Flash attention (causal + attention_mask), fp32 — unchanged this round.
// ---------------------------------------------------------------------------
__global__ void __launch_bounds__(128) flash_attn_kernel(
    const float* __restrict__ Q, const float* __restrict__ K,
    const float* __restrict__ V, const int* __restrict__ amask,
    float* __restrict__ O)
{
    __shared__ float Ks[64][DK];
    __shared__ float Vs[64][DK];
    __shared__ int   mskv[64];

    const int b = blockIdx.z;
    const int h = blockIdx.y;
    const int q0 = blockIdx.x * 128;
    const int t = threadIdx.x;
    const int qrow = q0 + t;

    const size_t head_base = ((size_t)(b * H_ + h)) * S_ * DK;
    const float* qptr = Q + head_base + (size_t)qrow * DK;
    const float* kbase = K + head_base;
    const float* vbase = V + head_base;
    const int* mbase = amask + b * S_;

    float q[DK];
    #pragma unroll
    for (int d = 0; d < DK; d += 4) {
        float4 v = *(const float4*)(qptr + d);
        q[d] = v.x; q[d + 1] = v.y; q[d + 2] = v.z; q[d + 3] = v.w;
    }

    float acc[DK];
    #pragma unroll
    for (int d = 0; d < DK; d++) acc[d] = 0.f;
    float mrun = NEG_BIG, lrun = 0.f;

    const int kend = q0 + 128;

    for (int k0 = 0; k0 < kend; k0 += 64) {
        #pragma unroll
        for (int i = 0; i < 8; i++) {
            const int idx = t + i * 128;
            const int r = idx >> 4;
            const int c = (idx & 15) * 4;
            *(float4*)&Ks[r][c] = *(const float4*)(kbase + (size_t)(k0 + r) * DK + c);
            *(float4*)&Vs[r][c] = *(const float4*)(vbase + (size_t)(k0 + r) * DK + c);
        }
        if (t < 64) mskv[t] = mbase[k0 + t];
        __syncthreads();

        #pragma unroll
        for (int half = 0; half < 2; half++) {
            const int kb = half * 32;
            if (k0 + kb > qrow) break;

            float p[32];
            float mloc = NEG_BIG;
            #pragma unroll
            for (int kk = 0; kk < 32; kk++) {
                const int kg = k0 + kb + kk;
                float s = 0.f;
                #pragma unroll
                for (int d = 0; d < DK; d++) s += q[d] * Ks[kb + kk][d];
                s *= 0.125f;
                const bool valid = (kg <= qrow) && (mskv[kb + kk] != 0);
                s = valid ? s : NEG_BIG;
                p[kk] = s;
                mloc = fmaxf(mloc, s);
            }
            const float mnew = fmaxf(mrun, mloc);
            const float corr = __expf(mrun - mnew);
            float lsum = 0.f;
            #pragma unroll
            for (int kk = 0; kk < 32; kk++) {
                const float e = (p[kk] == NEG_BIG) ? 0.f : __expf(p[kk] - mnew);
                p[kk] = e;
                lsum += e;
            }
            lrun = lrun * corr + lsum;
            #pragma unroll
            for (int d = 0; d < DK; d++) acc[d] *= corr;
            #pragma unroll
            for (int kk = 0; kk < 32; kk++) {
                const float pv = p[kk];
                #pragma unroll
                for (int d = 0; d < DK; d++) acc[d] += pv * Vs[kb + kk][d];
            }
            mrun = mnew;
        }
        __syncthreads();
    }

    const float inv = 1.f / lrun;
    float* optr = O + ((size_t)(b * S_) + qrow) * DM + h * DK;
    #pragma unroll
    for (int d = 0; d < DK; d += 4) {
        float4 v;
        v.x = acc[d] * inv; v.y = acc[d + 1] * inv;
        v.z = acc[d + 2] * inv; v.w = acc[d + 3] * inv;
        *(float4*)(optr + d) = v;
    }
}

// ---------------------------------------------------------------------------
// Launch
// ---------------------------------------------------------------------------
#define GEMM_SMEM 65536

extern "C" void kernel_launch(void* const* d_in, const int* in_sizes, int n_in,
                              void* d_out, int out_size)
{
    const float* x  = (const float*)d_in[0];
    const int*   am = (const int*)d_in[1];
    const float* wq = (const float*)d_in[2];
    const float* bq = (const float*)d_in[3];
    const float* wk = (const float*)d_in[4];
    const float* bk = (const float*)d_in[5];
    const float* wv = (const float*)d_in[6];
    const float* bv = (const float*)d_in[7];
    const float* wo = (const float*)d_in[8];
    const float* bo = (const float*)d_in[9];
    float* out = (float*)d_out;

    float *qp, *kp, *vp, *ap;
    cudaGetSymbolAddress((void**)&qp, g_q);
    cudaGetSymbolAddress((void**)&kp, g_k);
    cudaGetSymbolAddress((void**)&vp, g_v);
    cudaGetSymbolAddress((void**)&ap, g_att);

    cudaFuncSetAttribute(gemm_tc_kernel,
                         cudaFuncAttributeMaxDynamicSharedMemorySize, GEMM_SMEM);

    dim3 ggrid(DM / 128, MTOT / 128);   // (8, 32)
    gemm_tc_kernel<<<ggrid, 256, GEMM_SMEM>>>(x, wq, bq, qp, 0);
    gemm_tc_kernel<<<ggrid, 256, GEMM_SMEM>>>(x, wk, bk, kp, 0);
    gemm_tc_kernel<<<ggrid, 256, GEMM_SMEM>>>(x, wv, bv, vp, 0);

    dim3 agrid(S_ / 128, H_, B_);       // (16, 16, 2)
    flash_attn_kernel<<<agrid, 128>>>(qp, kp, vp, am, ap);

    gemm_tc_kernel<<<ggrid, 256, GEMM_SMEM>>>(ap, wo, bo, out, 1);
}

// round 4
// speedup vs baseline: 6.3364x; 4.2092x over previous
#include <cuda_runtime.h>
#include <cuda_bf16.h>
#include <math.h>
#include <cstdint>

// Problem constants
#define B_   2
#define S_   2048
#define DM   1024
#define H_   16
#define DK   64
#define MTOT (B_ * S_)   // 4096

// Scratch (device globals)
__device__ float g_att[MTOT * DM];                  // [B*S, DM]
__device__ __nv_bfloat16 g_qh[B_ * H_ * S_ * DK];   // hi/lo bf16 planes, [B,H,S,DK]
__device__ __nv_bfloat16 g_ql[B_ * H_ * S_ * DK];
__device__ __nv_bfloat16 g_kh[B_ * H_ * S_ * DK];
__device__ __nv_bfloat16 g_kl[B_ * H_ * S_ * DK];
__device__ __nv_bfloat16 g_vh[B_ * H_ * S_ * DK];
__device__ __nv_bfloat16 g_vl[B_ * H_ * S_ * DK];

__device__ __forceinline__ uint32_t smem_u32(const void* p) {
    uint32_t a;
    asm("{ .reg .u64 t; cvta.to.shared.u64 t, %1; cvt.u32.u64 %0, t; }"
        : "=r"(a) : "l"(p));
    return a;
}

#define CP_ASYNC16(dst, src) \
    asm volatile("cp.async.cg.shared.global [%0], [%1], 16;" :: "r"(dst), "l"(src))
#define CP_COMMIT() asm volatile("cp.async.commit_group;" ::: "memory")
#define CP_WAIT1()  asm volatile("cp.async.wait_group 1;" ::: "memory")

#define CVT_TF32(x) \
    asm volatile("cvt.rna.tf32.f32 %0, %1;" : "=r"(x) : "f"(__uint_as_float(x)))

#define LDSM_X4(r0, r1, r2, r3, addr) \
    asm volatile("ldmatrix.sync.aligned.m8n8.x4.shared.b16 {%0,%1,%2,%3}, [%4];" \
                 : "=r"(r0), "=r"(r1), "=r"(r2), "=r"(r3) : "r"(addr))

#define LDSM_X4_T(r0, r1, r2, r3, addr) \
    asm volatile("ldmatrix.sync.aligned.m8n8.x4.trans.shared.b16 {%0,%1,%2,%3}, [%4];" \
                 : "=r"(r0), "=r"(r1), "=r"(r2), "=r"(r3) : "r"(addr))

#define MMA_TF32(c, a, b) \
    asm volatile("mma.sync.aligned.m16n8k8.row.col.f32.tf32.tf32.f32 " \
                 "{%0,%1,%2,%3}, {%4,%5,%6,%7}, {%8,%9}, {%0,%1,%2,%3};" \
                 : "+f"((c)[0]), "+f"((c)[1]), "+f"((c)[2]), "+f"((c)[3]) \
                 : "r"((a)[0]), "r"((a)[1]), "r"((a)[2]), "r"((a)[3]), \
                   "r"((b)[0]), "r"((b)[1]))

#define MMA_BF16(c, a, b0, b1) \
    asm volatile("mma.sync.aligned.m16n8k16.row.col.f32.bf16.bf16.f32 " \
                 "{%0,%1,%2,%3}, {%4,%5,%6,%7}, {%8,%9}, {%0,%1,%2,%3};" \
                 : "+f"((c)[0]), "+f"((c)[1]), "+f"((c)[2]), "+f"((c)[3]) \
                 : "r"((a)[0]), "r"((a)[1]), "r"((a)[2]), "r"((a)[3]), \
                   "r"(b0), "r"(b1))

__device__ __forceinline__ void bsplit2(float x, float y, uint32_t& hi, uint32_t& lo) {
    __nv_bfloat162 h2, l2;
    h2.x = __float2bfloat16_rn(x);
    h2.y = __float2bfloat16_rn(y);
    l2.x = __float2bfloat16_rn(x - __bfloat162float(h2.x));
    l2.y = __float2bfloat16_rn(y - __bfloat162float(h2.y));
    hi = *reinterpret_cast<uint32_t*>(&h2);
    lo = *reinterpret_cast<uint32_t*>(&l2);
}

// ===========================================================================
// Tensor-core tf32 GEMM (NT): C[m,n] = sum_k A[m,k] * W[n,k] + bias[n]
// mode 0: write bf16 hi/lo planes, permuted to [B,H,S,DK]
// mode 1: write fp32 plain [M,N]
// ===========================================================================
__global__ void __launch_bounds__(256, 1) gemm_tc_kernel(
    const float* __restrict__ A, const float* __restrict__ W,
    const float* __restrict__ bias, float* __restrict__ C,
    __nv_bfloat16* __restrict__ Chi, __nv_bfloat16* __restrict__ Clo, int mode)
{
    extern __shared__ char smem[];
    const uint32_t sbase = smem_u32(smem);
    const int tid = threadIdx.x;
    const int lane = tid & 31;
    const int wid = tid >> 5;
    const int wm = wid >> 2;       // 0..1 (m)
    const int wn = wid & 3;        // 0..3 (n)
    const int m0 = blockIdx.y * 128;
    const int n0 = blockIdx.x * 128;

    int lrow[4], lkg[4];
    uint32_t ldst[4];
    #pragma unroll
    for (int it = 0; it < 4; it++) {
        const int c = tid + it * 256;
        const int r = c >> 3, kg = c & 7;
        lrow[it] = r; lkg[it] = kg;
        ldst[it] = (uint32_t)(r * 128 + ((kg ^ (r & 7)) * 16));
    }

    const int lrA = (lane & 7) + ((lane >> 3) & 1) * 8;
    const int lkA = lane >> 4;
    const int lrB = (lane & 7) + (lane >> 4) * 8;
    const int lkB = (lane >> 3) & 1;

    float acc[4][4][4];
    #pragma unroll
    for (int i = 0; i < 4; i++)
        #pragma unroll
        for (int j = 0; j < 4; j++)
            #pragma unroll
            for (int r = 0; r < 4; r++) acc[i][j][r] = 0.f;

    auto load_tiles = [&](int buf, int k0) {
        const uint32_t ab = sbase + buf * 32768u;
        const uint32_t bb = ab + 16384u;
        #pragma unroll
        for (int it = 0; it < 4; it++) {
            const float* ga = A + (size_t)(m0 + lrow[it]) * 1024 + k0 + lkg[it] * 4;
            const float* gb = W + (size_t)(n0 + lrow[it]) * 1024 + k0 + lkg[it] * 4;
            CP_ASYNC16(ab + ldst[it], ga);
            CP_ASYNC16(bb + ldst[it], gb);
        }
    };

    auto compute = [&](int buf) {
        const uint32_t ab = sbase + buf * 32768u;
        const uint32_t bb = ab + 16384u;
        #pragma unroll
        for (int ks = 0; ks < 4; ks++) {
            uint32_t a[4][4];
            #pragma unroll
            for (int mt = 0; mt < 4; mt++) {
                const uint32_t addr = ab +
                    (uint32_t)((wm * 64 + mt * 16 + lrA) * 128 +
                               (((ks * 2 + lkA) ^ (lrA & 7)) * 16));
                LDSM_X4(a[mt][0], a[mt][1], a[mt][2], a[mt][3], addr);
            }
            uint32_t b[4][2];
            #pragma unroll
            for (int np = 0; np < 2; np++) {
                const uint32_t addr = bb +
                    (uint32_t)((wn * 32 + np * 16 + lrB) * 128 +
                               (((ks * 2 + lkB) ^ (lrB & 7)) * 16));
                LDSM_X4(b[np * 2][0], b[np * 2][1], b[np * 2 + 1][0], b[np * 2 + 1][1], addr);
            }
            #pragma unroll
            for (int mt = 0; mt < 4; mt++)
                #pragma unroll
                for (int j = 0; j < 4; j++) CVT_TF32(a[mt][j]);
            #pragma unroll
            for (int nt = 0; nt < 4; nt++) {
                CVT_TF32(b[nt][0]); CVT_TF32(b[nt][1]);
            }
            #pragma unroll
            for (int mt = 0; mt < 4; mt++)
                #pragma unroll
                for (int nt = 0; nt < 4; nt++)
                    MMA_TF32(acc[mt][nt], a[mt], b[nt]);
        }
    };

    load_tiles(0, 0);  CP_COMMIT();
    load_tiles(1, 32); CP_COMMIT();

    for (int i = 0; i < 32; i++) {
        CP_WAIT1();
        __syncthreads();
        compute(i & 1);
        __syncthreads();
        if (i + 2 < 32) load_tiles(i & 1, (i + 2) * 32);
        CP_COMMIT();
    }

    const int lr = lane >> 2;
    const int lc = (lane & 3) * 2;
    #pragma unroll
    for (int mt = 0; mt < 4; mt++) {
        const int m = m0 + wm * 64 + mt * 16 + lr;
        #pragma unroll
        for (int nt = 0; nt < 4; nt++) {
            const int n = n0 + wn * 32 + nt * 8 + lc;
            const float b0 = __ldg(bias + n);
            const float b1 = __ldg(bias + n + 1);
            float v00 = acc[mt][nt][0] + b0, v01 = acc[mt][nt][1] + b1;
            float v10 = acc[mt][nt][2] + b0, v11 = acc[mt][nt][3] + b1;
            if (mode == 0) {
                const int bb = m >> 11;
                const int s  = m & 2047;
                const int h  = n >> 6;
                const int d  = n & 63;
                const size_t i0 = (((size_t)(bb * H_ + h) * S_) + s) * DK + d;
                uint32_t h0, l0, h1, l1;
                bsplit2(v00, v01, h0, l0);
                bsplit2(v10, v11, h1, l1);
                *reinterpret_cast<uint32_t*>(Chi + i0) = h0;
                *reinterpret_cast<uint32_t*>(Clo + i0) = l0;
                *reinterpret_cast<uint32_t*>(Chi + i0 + 8 * DK) = h1;
                *reinterpret_cast<uint32_t*>(Clo + i0 + 8 * DK) = l1;
            } else {
                float* p0 = C + (size_t)m * DM + n;
                *(float2*)p0 = make_float2(v00, v01);
                *(float2*)(p0 + 8 * DM) = make_float2(v10, v11);
            }
        }
    }
}

// ===========================================================================
// Tensor-core flash attention, bf16 split-3 compensated MMA.
// Grid (S/64, H, B), 128 threads (4 warps x 16 q-rows).
// ===========================================================================
#define FA_QH 0
#define FA_QL 8192
#define FA_KH 16384
#define FA_KL 24576
#define FA_VH 32768
#define FA_VL 40960
#define FA_MSK 49152
#define FA_SMEM (49152 + 256)

__global__ void __launch_bounds__(128) flash_attn_tc(
    const __nv_bfloat16* __restrict__ Qh, const __nv_bfloat16* __restrict__ Ql,
    const __nv_bfloat16* __restrict__ Kh, const __nv_bfloat16* __restrict__ Kl,
    const __nv_bfloat16* __restrict__ Vh, const __nv_bfloat16* __restrict__ Vl,
    const int* __restrict__ amask, float* __restrict__ O)
{
    extern __shared__ char fs[];
    const int b = blockIdx.z;
    const int h = blockIdx.y;
    const int q0 = (gridDim.x - 1 - blockIdx.x) * 64;   // heavy tiles first
    const int tid = threadIdx.x;
    const int lane = tid & 31;
    const int wid = tid >> 5;
    const size_t hb = ((size_t)(b * H_ + h)) * S_ * DK;
    int* smask = (int*)(fs + FA_MSK);

    // Q tile load (swizzled)
    #pragma unroll
    for (int it = 0; it < 4; it++) {
        const int idx = tid + it * 128;
        const int r = idx >> 3, c = idx & 7;
        const uint32_t sw = (uint32_t)(r * 128 + ((c ^ (r & 7)) * 16));
        const size_t g = hb + (size_t)(q0 + r) * DK + c * 8;
        *(uint4*)(fs + FA_QH + sw) = *(const uint4*)(Qh + g);
        *(uint4*)(fs + FA_QL + sw) = *(const uint4*)(Ql + g);
    }
    __syncthreads();

    // Q fragments (A-frag of m16n8k16)
    const int lrA = (lane & 7) + ((lane >> 3) & 1) * 8;
    const int lkA = lane >> 4;
    uint32_t qfh[4][4], qfl[4][4];
    {
        const uint32_t qbh = smem_u32(fs + FA_QH);
        const uint32_t qbl = smem_u32(fs + FA_QL);
        const int row = wid * 16 + lrA;
        #pragma unroll
        for (int ks = 0; ks < 4; ks++) {
            const uint32_t off = (uint32_t)(row * 128 + (((ks * 2 + lkA) ^ (row & 7)) * 16));
            LDSM_X4(qfh[ks][0], qfh[ks][1], qfh[ks][2], qfh[ks][3], qbh + off);
            LDSM_X4(qfl[ks][0], qfl[ks][1], qfl[ks][2], qfl[ks][3], qbl + off);
        }
    }

    const int rlo = q0 + wid * 16 + (lane >> 2);
    const int rhi = rlo + 8;
    const int cb = (lane & 3) * 2;
    const int lrB = (lane & 7) + ((lane >> 4) & 1) * 8;
    const int lkB = (lane >> 3) & 1;
    const int vlr = (lane & 7) + ((lane >> 3) & 1) * 8;
    const int vck = lane >> 4;

    float o[8][4];
    #pragma unroll
    for (int j = 0; j < 8; j++)
        #pragma unroll
        for (int r = 0; r < 4; r++) o[j][r] = 0.f;
    float m_lo = -1e30f, m_hi = -1e30f, l_lo = 0.f, l_hi = 0.f;

    for (int k0 = 0; k0 <= q0; k0 += 64) {
        // K/V tile loads
        #pragma unroll
        for (int it = 0; it < 4; it++) {
            const int idx = tid + it * 128;
            const int r = idx >> 3, c = idx & 7;
            const uint32_t sw = (uint32_t)(r * 128 + ((c ^ (r & 7)) * 16));
            const size_t g = hb + (size_t)(k0 + r) * DK + c * 8;
            *(uint4*)(fs + FA_KH + sw) = *(const uint4*)(Kh + g);
            *(uint4*)(fs + FA_KL + sw) = *(const uint4*)(Kl + g);
            *(uint4*)(fs + FA_VH + sw) = *(const uint4*)(Vh + g);
            *(uint4*)(fs + FA_VL + sw) = *(const uint4*)(Vl + g);
        }
        if (tid < 64) smask[tid] = amask[b * S_ + k0 + tid];
        __syncthreads();

        // ---- scores: S = Qh*Kh + Qh*Kl + Ql*Kh
        float s[8][4];
        #pragma unroll
        for (int j = 0; j < 8; j++)
            #pragma unroll
            for (int r = 0; r < 4; r++) s[j][r] = 0.f;

        const uint32_t kbh = smem_u32(fs + FA_KH);
        const uint32_t kbl = smem_u32(fs + FA_KL);
        #pragma unroll
        for (int jp = 0; jp < 4; jp++) {
            const int rowb = jp * 16 + lrB;
            #pragma unroll
            for (int ks = 0; ks < 4; ks++) {
                const uint32_t off = (uint32_t)(rowb * 128 + (((ks * 2 + lkB) ^ (rowb & 7)) * 16));
                uint32_t bh0, bh1, bh2, bh3, bl0, bl1, bl2, bl3;
                LDSM_X4(bh0, bh1, bh2, bh3, kbh + off);
                LDSM_X4(bl0, bl1, bl2, bl3, kbl + off);
                MMA_BF16(s[2 * jp],     qfh[ks], bh0, bh1);
                MMA_BF16(s[2 * jp],     qfh[ks], bl0, bl1);
                MMA_BF16(s[2 * jp],     qfl[ks], bh0, bh1);
                MMA_BF16(s[2 * jp + 1], qfh[ks], bh2, bh3);
                MMA_BF16(s[2 * jp + 1], qfh[ks], bl2, bl3);
                MMA_BF16(s[2 * jp + 1], qfl[ks], bh2, bh3);
            }
        }

        // ---- mask + online softmax
        float mloc_lo = -1e30f, mloc_hi = -1e30f;
        #pragma unroll
        for (int j = 0; j < 8; j++) {
            const int c0 = k0 + j * 8 + cb;
            const int c1 = c0 + 1;
            const bool mv0 = smask[j * 8 + cb] != 0;
            const bool mv1 = smask[j * 8 + cb + 1] != 0;
            s[j][0] = (mv0 && c0 <= rlo) ? s[j][0] * 0.125f : -1e30f;
            s[j][1] = (mv1 && c1 <= rlo) ? s[j][1] * 0.125f : -1e30f;
            s[j][2] = (mv0 && c0 <= rhi) ? s[j][2] * 0.125f : -1e30f;
            s[j][3] = (mv1 && c1 <= rhi) ? s[j][3] * 0.125f : -1e30f;
            mloc_lo = fmaxf(mloc_lo, fmaxf(s[j][0], s[j][1]));
            mloc_hi = fmaxf(mloc_hi, fmaxf(s[j][2], s[j][3]));
        }
        mloc_lo = fmaxf(mloc_lo, __shfl_xor_sync(0xFFFFFFFFu, mloc_lo, 1));
        mloc_lo = fmaxf(mloc_lo, __shfl_xor_sync(0xFFFFFFFFu, mloc_lo, 2));
        mloc_hi = fmaxf(mloc_hi, __shfl_xor_sync(0xFFFFFFFFu, mloc_hi, 1));
        mloc_hi = fmaxf(mloc_hi, __shfl_xor_sync(0xFFFFFFFFu, mloc_hi, 2));

        const float mnew_lo = fmaxf(m_lo, mloc_lo);
        const float mnew_hi = fmaxf(m_hi, mloc_hi);
        const float corr_lo = __expf(m_lo - mnew_lo);
        const float corr_hi = __expf(m_hi - mnew_hi);

        float ls_lo = 0.f, ls_hi = 0.f;
        #pragma unroll
        for (int j = 0; j < 8; j++) {
            s[j][0] = __expf(s[j][0] - mnew_lo);
            s[j][1] = __expf(s[j][1] - mnew_lo);
            s[j][2] = __expf(s[j][2] - mnew_hi);
            s[j][3] = __expf(s[j][3] - mnew_hi);
            ls_lo += s[j][0] + s[j][1];
            ls_hi += s[j][2] + s[j][3];
        }
        ls_lo += __shfl_xor_sync(0xFFFFFFFFu, ls_lo, 1);
        ls_lo += __shfl_xor_sync(0xFFFFFFFFu, ls_lo, 2);
        ls_hi += __shfl_xor_sync(0xFFFFFFFFu, ls_hi, 1);
        ls_hi += __shfl_xor_sync(0xFFFFFFFFu, ls_hi, 2);

        l_lo = l_lo * corr_lo + ls_lo;
        l_hi = l_hi * corr_hi + ls_hi;
        m_lo = mnew_lo; m_hi = mnew_hi;

        #pragma unroll
        for (int j = 0; j < 8; j++) {
            o[j][0] *= corr_lo; o[j][1] *= corr_lo;
            o[j][2] *= corr_hi; o[j][3] *= corr_hi;
        }

        // ---- PV: O += Ph*Vh + Pl*Vh + Ph*Vl
        const uint32_t vbh = smem_u32(fs + FA_VH);
        const uint32_t vbl = smem_u32(fs + FA_VL);
        #pragma unroll
        for (int t = 0; t < 4; t++) {
            uint32_t ah[4], al[4];
            bsplit2(s[2 * t][0],     s[2 * t][1],     ah[0], al[0]);
            bsplit2(s[2 * t][2],     s[2 * t][3],     ah[1], al[1]);
            bsplit2(s[2 * t + 1][0], s[2 * t + 1][1], ah[2], al[2]);
            bsplit2(s[2 * t + 1][2], s[2 * t + 1][3], ah[3], al[3]);
            const int vrow = t * 16 + vlr;
            #pragma unroll
            for (int ndp = 0; ndp < 4; ndp++) {
                const uint32_t off = (uint32_t)(vrow * 128 + (((ndp * 2 + vck) ^ (vrow & 7)) * 16));
                uint32_t vh0, vh1, vh2, vh3, vl0, vl1, vl2, vl3;
                LDSM_X4_T(vh0, vh1, vh2, vh3, vbh + off);
                LDSM_X4_T(vl0, vl1, vl2, vl3, vbl + off);
                MMA_BF16(o[2 * ndp],     ah, vh0, vh1);
                MMA_BF16(o[2 * ndp],     al, vh0, vh1);
                MMA_BF16(o[2 * ndp],     ah, vl0, vl1);
                MMA_BF16(o[2 * ndp + 1], ah, vh2, vh3);
                MMA_BF16(o[2 * ndp + 1], al, vh2, vh3);
                MMA_BF16(o[2 * ndp + 1], ah, vl2, vl3);
            }
        }
        __syncthreads();
    }

    const float inv_lo = 1.f / l_lo;
    const float inv_hi = 1.f / l_hi;
    float* base_lo = O + ((size_t)(b * S_) + rlo) * DM + h * DK;
    float* base_hi = O + ((size_t)(b * S_) + rhi) * DM + h * DK;
    #pragma unroll
    for (int j = 0; j < 8; j++) {
        const int d = j * 8 + cb;
        *(float2*)(base_lo + d) = make_float2(o[j][0] * inv_lo, o[j][1] * inv_lo);
        *(float2*)(base_hi + d) = make_float2(o[j][2] * inv_hi, o[j][3] * inv_hi);
    }
}

// ---------------------------------------------------------------------------
// Launch
// ---------------------------------------------------------------------------
#define GEMM_SMEM 65536

extern "C" void kernel_launch(void* const* d_in, const int* in_sizes, int n_in,
                              void* d_out, int out_size)
{
    const float* x  = (const float*)d_in[0];
    const int*   am = (const int*)d_in[1];
    const float* wq = (const float*)d_in[2];
    const float* bq = (const float*)d_in[3];
    const float* wk = (const float*)d_in[4];
    const float* bk = (const float*)d_in[5];
    const float* wv = (const float*)d_in[6];
    const float* bv = (const float*)d_in[7];
    const float* wo = (const float*)d_in[8];
    const float* bo = (const float*)d_in[9];
    float* out = (float*)d_out;

    float* ap;
    __nv_bfloat16 *qh, *ql, *kh, *kl, *vh, *vl;
    cudaGetSymbolAddress((void**)&ap, g_att);
    cudaGetSymbolAddress((void**)&qh, g_qh);
    cudaGetSymbolAddress((void**)&ql, g_ql);
    cudaGetSymbolAddress((void**)&kh, g_kh);
    cudaGetSymbolAddress((void**)&kl, g_kl);
    cudaGetSymbolAddress((void**)&vh, g_vh);
    cudaGetSymbolAddress((void**)&vl, g_vl);

    cudaFuncSetAttribute(gemm_tc_kernel,
                         cudaFuncAttributeMaxDynamicSharedMemorySize, GEMM_SMEM);
    cudaFuncSetAttribute(flash_attn_tc,
                         cudaFuncAttributeMaxDynamicSharedMemorySize, FA_SMEM);

    dim3 ggrid(DM / 128, MTOT / 128);   // (8, 32)
    gemm_tc_kernel<<<ggrid, 256, GEMM_SMEM>>>(x, wq, bq, nullptr, qh, ql, 0);
    gemm_tc_kernel<<<ggrid, 256, GEMM_SMEM>>>(x, wk, bk, nullptr, kh, kl, 0);
    gemm_tc_kernel<<<ggrid, 256, GEMM_SMEM>>>(x, wv, bv, nullptr, vh, vl, 0);

    dim3 agrid(S_ / 64, H_, B_);        // (32, 16, 2)
    flash_attn_tc<<<agrid, 128, FA_SMEM>>>(qh, ql, kh, kl, vh, vl, am, ap);

    gemm_tc_kernel<<<ggrid, 256, GEMM_SMEM>>>(ap, wo, bo, out, nullptr, nullptr, 1);
}

// round 5
// speedup vs baseline: 6.8027x; 1.0736x over previous
#include <cuda_runtime.h>
#include <cuda_bf16.h>
#include <math.h>
#include <cstdint>

// Problem constants
#define B_   2
#define S_   2048
#define DM   1024
#define H_   16
#define DK   64
#define MTOT (B_ * S_)   // 4096

// Scratch (device globals)
__device__ float g_att[MTOT * DM];                  // [B*S, DM] (tf32-rounded)
__device__ float g_xc[MTOT * DM];                   // x pre-rounded to tf32
__device__ float g_wc[4][DM * DM];                  // w_q,w_k,w_v,w_o pre-rounded
__device__ __nv_bfloat16 g_qh[B_ * H_ * S_ * DK];   // hi/lo bf16 planes, [B,H,S,DK]
__device__ __nv_bfloat16 g_ql[B_ * H_ * S_ * DK];
__device__ __nv_bfloat16 g_kh[B_ * H_ * S_ * DK];
__device__ __nv_bfloat16 g_kl[B_ * H_ * S_ * DK];
__device__ __nv_bfloat16 g_vh[B_ * H_ * S_ * DK];
__device__ __nv_bfloat16 g_vl[B_ * H_ * S_ * DK];

__device__ __forceinline__ uint32_t smem_u32(const void* p) {
    uint32_t a;
    asm("{ .reg .u64 t; cvta.to.shared.u64 t, %1; cvt.u32.u64 %0, t; }"
        : "=r"(a) : "l"(p));
    return a;
}

#define CP_ASYNC16(dst, src) \
    asm volatile("cp.async.cg.shared.global [%0], [%1], 16;" :: "r"(dst), "l"(src))
#define CP_ASYNC4(dst, src) \
    asm volatile("cp.async.ca.shared.global [%0], [%1], 4;" :: "r"(dst), "l"(src))
#define CP_COMMIT() asm volatile("cp.async.commit_group;" ::: "memory")
#define CP_WAIT1()  asm volatile("cp.async.wait_group 1;" ::: "memory")
#define CP_WAIT0()  asm volatile("cp.async.wait_group 0;" ::: "memory")

__device__ __forceinline__ float tf32_rna(float x) {
    uint32_t u;
    asm("cvt.rna.tf32.f32 %0, %1;" : "=r"(u) : "f"(x));
    return __uint_as_float(u);
}

#define LDSM_X4(r0, r1, r2, r3, addr) \
    asm volatile("ldmatrix.sync.aligned.m8n8.x4.shared.b16 {%0,%1,%2,%3}, [%4];" \
                 : "=r"(r0), "=r"(r1), "=r"(r2), "=r"(r3) : "r"(addr))

#define LDSM_X4_T(r0, r1, r2, r3, addr) \
    asm volatile("ldmatrix.sync.aligned.m8n8.x4.trans.shared.b16 {%0,%1,%2,%3}, [%4];" \
                 : "=r"(r0), "=r"(r1), "=r"(r2), "=r"(r3) : "r"(addr))

#define MMA_TF32(c, a, b) \
    asm volatile("mma.sync.aligned.m16n8k8.row.col.f32.tf32.tf32.f32 " \
                 "{%0,%1,%2,%3}, {%4,%5,%6,%7}, {%8,%9}, {%0,%1,%2,%3};" \
                 : "+f"((c)[0]), "+f"((c)[1]), "+f"((c)[2]), "+f"((c)[3]) \
                 : "r"((a)[0]), "r"((a)[1]), "r"((a)[2]), "r"((a)[3]), \
                   "r"((b)[0]), "r"((b)[1]))

#define MMA_BF16(c, a, b0, b1) \
    asm volatile("mma.sync.aligned.m16n8k16.row.col.f32.bf16.bf16.f32 " \
                 "{%0,%1,%2,%3}, {%4,%5,%6,%7}, {%8,%9}, {%0,%1,%2,%3};" \
                 : "+f"((c)[0]), "+f"((c)[1]), "+f"((c)[2]), "+f"((c)[3]) \
                 : "r"((a)[0]), "r"((a)[1]), "r"((a)[2]), "r"((a)[3]), \
                   "r"(b0), "r"(b1))

__device__ __forceinline__ void bsplit2(float x, float y, uint32_t& hi, uint32_t& lo) {
    __nv_bfloat162 h2, l2;
    h2.x = __float2bfloat16_rn(x);
    h2.y = __float2bfloat16_rn(y);
    l2.x = __float2bfloat16_rn(x - __bfloat162float(h2.x));
    l2.y = __float2bfloat16_rn(y - __bfloat162float(h2.y));
    hi = *reinterpret_cast<uint32_t*>(&h2);
    lo = *reinterpret_cast<uint32_t*>(&l2);
}

// ===========================================================================
// Elementwise pre-round to tf32 (rna), float4 grid-stride.
// ===========================================================================
__global__ void tf32_round_kernel(const float4* __restrict__ in,
                                  float4* __restrict__ out, int n4)
{
    for (int i = blockIdx.x * blockDim.x + threadIdx.x; i < n4;
         i += gridDim.x * blockDim.x) {
        float4 v = in[i];
        v.x = tf32_rna(v.x); v.y = tf32_rna(v.y);
        v.z = tf32_rna(v.z); v.w = tf32_rna(v.w);
        out[i] = v;
    }
}

// ===========================================================================
// Tensor-core tf32 GEMM (NT), inputs pre-rounded to tf32 (no in-loop cvt).
// mode 0: write bf16 hi/lo planes, permuted to [B,H,S,DK];  mode 1: fp32 [M,N]
// ===========================================================================
__global__ void __launch_bounds__(256, 1) gemm_tc_kernel(
    const float* __restrict__ A, const float* __restrict__ W,
    const float* __restrict__ bias, float* __restrict__ C,
    __nv_bfloat16* __restrict__ Chi, __nv_bfloat16* __restrict__ Clo, int mode)
{
    extern __shared__ char smem[];
    const uint32_t sbase = smem_u32(smem);
    const int tid = threadIdx.x;
    const int lane = tid & 31;
    const int wid = tid >> 5;
    const int wm = wid >> 2;
    const int wn = wid & 3;
    const int m0 = blockIdx.y * 128;
    const int n0 = blockIdx.x * 128;

    int lrow[4], lkg[4];
    uint32_t ldst[4];
    #pragma unroll
    for (int it = 0; it < 4; it++) {
        const int c = tid + it * 256;
        const int r = c >> 3, kg = c & 7;
        lrow[it] = r; lkg[it] = kg;
        ldst[it] = (uint32_t)(r * 128 + ((kg ^ (r & 7)) * 16));
    }

    const int lrA = (lane & 7) + ((lane >> 3) & 1) * 8;
    const int lkA = lane >> 4;
    const int lrB = (lane & 7) + (lane >> 4) * 8;
    const int lkB = (lane >> 3) & 1;

    float acc[4][4][4];
    #pragma unroll
    for (int i = 0; i < 4; i++)
        #pragma unroll
        for (int j = 0; j < 4; j++)
            #pragma unroll
            for (int r = 0; r < 4; r++) acc[i][j][r] = 0.f;

    auto load_tiles = [&](int buf, int k0) {
        const uint32_t ab = sbase + buf * 32768u;
        const uint32_t bb = ab + 16384u;
        #pragma unroll
        for (int it = 0; it < 4; it++) {
            const float* ga = A + (size_t)(m0 + lrow[it]) * 1024 + k0 + lkg[it] * 4;
            const float* gb = W + (size_t)(n0 + lrow[it]) * 1024 + k0 + lkg[it] * 4;
            CP_ASYNC16(ab + ldst[it], ga);
            CP_ASYNC16(bb + ldst[it], gb);
        }
    };

    auto compute = [&](int buf) {
        const uint32_t ab = sbase + buf * 32768u;
        const uint32_t bb = ab + 16384u;
        #pragma unroll
        for (int ks = 0; ks < 4; ks++) {
            uint32_t a[4][4];
            #pragma unroll
            for (int mt = 0; mt < 4; mt++) {
                const uint32_t addr = ab +
                    (uint32_t)((wm * 64 + mt * 16 + lrA) * 128 +
                               (((ks * 2 + lkA) ^ (lrA & 7)) * 16));
                LDSM_X4(a[mt][0], a[mt][1], a[mt][2], a[mt][3], addr);
            }
            uint32_t b[4][2];
            #pragma unroll
            for (int np = 0; np < 2; np++) {
                const uint32_t addr = bb +
                    (uint32_t)((wn * 32 + np * 16 + lrB) * 128 +
                               (((ks * 2 + lkB) ^ (lrB & 7)) * 16));
                LDSM_X4(b[np * 2][0], b[np * 2][1], b[np * 2 + 1][0], b[np * 2 + 1][1], addr);
            }
            #pragma unroll
            for (int mt = 0; mt < 4; mt++)
                #pragma unroll
                for (int nt = 0; nt < 4; nt++)
                    MMA_TF32(acc[mt][nt], a[mt], b[nt]);
        }
    };

    load_tiles(0, 0);  CP_COMMIT();
    load_tiles(1, 32); CP_COMMIT();

    for (int i = 0; i < 32; i++) {
        CP_WAIT1();
        __syncthreads();
        compute(i & 1);
        __syncthreads();
        if (i + 2 < 32) load_tiles(i & 1, (i + 2) * 32);
        CP_COMMIT();
    }

    const int lr = lane >> 2;
    const int lc = (lane & 3) * 2;
    #pragma unroll
    for (int mt = 0; mt < 4; mt++) {
        const int m = m0 + wm * 64 + mt * 16 + lr;
        #pragma unroll
        for (int nt = 0; nt < 4; nt++) {
            const int n = n0 + wn * 32 + nt * 8 + lc;
            const float b0 = __ldg(bias + n);
            const float b1 = __ldg(bias + n + 1);
            float v00 = acc[mt][nt][0] + b0, v01 = acc[mt][nt][1] + b1;
            float v10 = acc[mt][nt][2] + b0, v11 = acc[mt][nt][3] + b1;
            if (mode == 0) {
                const int bb = m >> 11;
                const int s  = m & 2047;
                const int h  = n >> 6;
                const int d  = n & 63;
                const size_t i0 = (((size_t)(bb * H_ + h) * S_) + s) * DK + d;
                uint32_t h0, l0, h1, l1;
                bsplit2(v00, v01, h0, l0);
                bsplit2(v10, v11, h1, l1);
                *reinterpret_cast<uint32_t*>(Chi + i0) = h0;
                *reinterpret_cast<uint32_t*>(Clo + i0) = l0;
                *reinterpret_cast<uint32_t*>(Chi + i0 + 8 * DK) = h1;
                *reinterpret_cast<uint32_t*>(Clo + i0 + 8 * DK) = l1;
            } else {
                float* p0 = C + (size_t)m * DM + n;
                *(float2*)p0 = make_float2(v00, v01);
                *(float2*)(p0 + 8 * DM) = make_float2(v10, v11);
            }
        }
    }
}

// ===========================================================================
// Tensor-core flash attention, bf16 split-3, cp.async double-buffered K/V.
// Grid (S/64, H, B), 128 threads (4 warps x 16 q-rows).
// ===========================================================================
#define FA_QH  0
#define FA_QL  8192
#define FA_BUF 16384                  // + buf*32768 : KH, KL, VH, VL (8KB each)
#define FA_MSK 81920                  // + buf*256
#define FA_SMEM (81920 + 512)

__global__ void __launch_bounds__(128) flash_attn_tc(
    const __nv_bfloat16* __restrict__ Qh, const __nv_bfloat16* __restrict__ Ql,
    const __nv_bfloat16* __restrict__ Kh, const __nv_bfloat16* __restrict__ Kl,
    const __nv_bfloat16* __restrict__ Vh, const __nv_bfloat16* __restrict__ Vl,
    const int* __restrict__ amask, float* __restrict__ O)
{
    extern __shared__ char fs[];
    const uint32_t sbase = smem_u32(fs);
    const int b = blockIdx.z;
    const int h = blockIdx.y;
    const int q0 = (gridDim.x - 1 - blockIdx.x) * 64;   // heavy tiles first
    const int tid = threadIdx.x;
    const int lane = tid & 31;
    const int wid = tid >> 5;
    const size_t hb = ((size_t)(b * H_ + h)) * S_ * DK;

    auto load_kv = [&](int buf, int k0) {
        const uint32_t base = sbase + FA_BUF + buf * 32768u;
        #pragma unroll
        for (int it = 0; it < 4; it++) {
            const int c = tid + it * 128;
            const int r = c >> 3, kg = c & 7;
            const uint32_t sw = (uint32_t)(r * 128 + ((kg ^ (r & 7)) * 16));
            const size_t g = hb + (size_t)(k0 + r) * DK + kg * 8;
            CP_ASYNC16(base + sw,          Kh + g);
            CP_ASYNC16(base + 8192 + sw,   Kl + g);
            CP_ASYNC16(base + 16384 + sw,  Vh + g);
            CP_ASYNC16(base + 24576 + sw,  Vl + g);
        }
        if (tid < 64)
            CP_ASYNC4(sbase + FA_MSK + buf * 256u + tid * 4,
                      amask + b * S_ + k0 + tid);
    };

    // Q tile load (swizzled, one-time)
    #pragma unroll
    for (int it = 0; it < 4; it++) {
        const int idx = tid + it * 128;
        const int r = idx >> 3, c = idx & 7;
        const uint32_t sw = (uint32_t)(r * 128 + ((c ^ (r & 7)) * 16));
        const size_t g = hb + (size_t)(q0 + r) * DK + c * 8;
        *(uint4*)(fs + FA_QH + sw) = *(const uint4*)(Qh + g);
        *(uint4*)(fs + FA_QL + sw) = *(const uint4*)(Ql + g);
    }
    load_kv(0, 0);
    CP_COMMIT();
    __syncthreads();

    // Q fragments
    const int lrA = (lane & 7) + ((lane >> 3) & 1) * 8;
    const int lkA = lane >> 4;
    uint32_t qfh[4][4], qfl[4][4];
    {
        const uint32_t qbh = sbase + FA_QH;
        const uint32_t qbl = sbase + FA_QL;
        const int row = wid * 16 + lrA;
        #pragma unroll
        for (int ks = 0; ks < 4; ks++) {
            const uint32_t off = (uint32_t)(row * 128 + (((ks * 2 + lkA) ^ (row & 7)) * 16));
            LDSM_X4(qfh[ks][0], qfh[ks][1], qfh[ks][2], qfh[ks][3], qbh + off);
            LDSM_X4(qfl[ks][0], qfl[ks][1], qfl[ks][2], qfl[ks][3], qbl + off);
        }
    }

    const int rlo = q0 + wid * 16 + (lane >> 2);
    const int rhi = rlo + 8;
    const int cb = (lane & 3) * 2;
    const int lrB = (lane & 7) + ((lane >> 4) & 1) * 8;
    const int lkB = (lane >> 3) & 1;
    const int vlr = (lane & 7) + ((lane >> 3) & 1) * 8;
    const int vck = lane >> 4;

    float o[8][4];
    #pragma unroll
    for (int j = 0; j < 8; j++)
        #pragma unroll
        for (int r = 0; r < 4; r++) o[j][r] = 0.f;
    float m_lo = -1e30f, m_hi = -1e30f, l_lo = 0.f, l_hi = 0.f;

    const int ntiles = q0 / 64 + 1;
    for (int i = 0; i < ntiles; i++) {
        const int k0 = i * 64;
        const int buf = i & 1;
        if (i + 1 < ntiles) {
            load_kv((i + 1) & 1, k0 + 64);
            CP_COMMIT();
            CP_WAIT1();
        } else {
            CP_WAIT0();
        }
        __syncthreads();

        const int* smask = (const int*)(fs + FA_MSK + buf * 256);
        const uint32_t kbh = sbase + FA_BUF + buf * 32768u;
        const uint32_t kbl = kbh + 8192u;
        const uint32_t vbh = kbh + 16384u;
        const uint32_t vbl = kbh + 24576u;

        // ---- scores: S = Qh*Kh + Qh*Kl + Ql*Kh
        float s[8][4];
        #pragma unroll
        for (int j = 0; j < 8; j++)
            #pragma unroll
            for (int r = 0; r < 4; r++) s[j][r] = 0.f;

        #pragma unroll
        for (int jp = 0; jp < 4; jp++) {
            const int rowb = jp * 16 + lrB;
            #pragma unroll
            for (int ks = 0; ks < 4; ks++) {
                const uint32_t off = (uint32_t)(rowb * 128 + (((ks * 2 + lkB) ^ (rowb & 7)) * 16));
                uint32_t bh0, bh1, bh2, bh3, bl0, bl1, bl2, bl3;
                LDSM_X4(bh0, bh1, bh2, bh3, kbh + off);
                LDSM_X4(bl0, bl1, bl2, bl3, kbl + off);
                MMA_BF16(s[2 * jp],     qfh[ks], bh0, bh1);
                MMA_BF16(s[2 * jp],     qfh[ks], bl0, bl1);
                MMA_BF16(s[2 * jp],     qfl[ks], bh0, bh1);
                MMA_BF16(s[2 * jp + 1], qfh[ks], bh2, bh3);
                MMA_BF16(s[2 * jp + 1], qfh[ks], bl2, bl3);
                MMA_BF16(s[2 * jp + 1], qfl[ks], bh2, bh3);
            }
        }

        // ---- mask + online softmax
        float mloc_lo = -1e30f, mloc_hi = -1e30f;
        #pragma unroll
        for (int j = 0; j < 8; j++) {
            const int c0 = k0 + j * 8 + cb;
            const int c1 = c0 + 1;
            const bool mv0 = smask[j * 8 + cb] != 0;
            const bool mv1 = smask[j * 8 + cb + 1] != 0;
            s[j][0] = (mv0 && c0 <= rlo) ? s[j][0] * 0.125f : -1e30f;
            s[j][1] = (mv1 && c1 <= rlo) ? s[j][1] * 0.125f : -1e30f;
            s[j][2] = (mv0 && c0 <= rhi) ? s[j][2] * 0.125f : -1e30f;
            s[j][3] = (mv1 && c1 <= rhi) ? s[j][3] * 0.125f : -1e30f;
            mloc_lo = fmaxf(mloc_lo, fmaxf(s[j][0], s[j][1]));
            mloc_hi = fmaxf(mloc_hi, fmaxf(s[j][2], s[j][3]));
        }
        mloc_lo = fmaxf(mloc_lo, __shfl_xor_sync(0xFFFFFFFFu, mloc_lo, 1));
        mloc_lo = fmaxf(mloc_lo, __shfl_xor_sync(0xFFFFFFFFu, mloc_lo, 2));
        mloc_hi = fmaxf(mloc_hi, __shfl_xor_sync(0xFFFFFFFFu, mloc_hi, 1));
        mloc_hi = fmaxf(mloc_hi, __shfl_xor_sync(0xFFFFFFFFu, mloc_hi, 2));

        const float mnew_lo = fmaxf(m_lo, mloc_lo);
        const float mnew_hi = fmaxf(m_hi, mloc_hi);
        const float corr_lo = __expf(m_lo - mnew_lo);
        const float corr_hi = __expf(m_hi - mnew_hi);

        float ls_lo = 0.f, ls_hi = 0.f;
        #pragma unroll
        for (int j = 0; j < 8; j++) {
            s[j][0] = __expf(s[j][0] - mnew_lo);
            s[j][1] = __expf(s[j][1] - mnew_lo);
            s[j][2] = __expf(s[j][2] - mnew_hi);
            s[j][3] = __expf(s[j][3] - mnew_hi);
            ls_lo += s[j][0] + s[j][1];
            ls_hi += s[j][2] + s[j][3];
        }
        ls_lo += __shfl_xor_sync(0xFFFFFFFFu, ls_lo, 1);
        ls_lo += __shfl_xor_sync(0xFFFFFFFFu, ls_lo, 2);
        ls_hi += __shfl_xor_sync(0xFFFFFFFFu, ls_hi, 1);
        ls_hi += __shfl_xor_sync(0xFFFFFFFFu, ls_hi, 2);

        l_lo = l_lo * corr_lo + ls_lo;
        l_hi = l_hi * corr_hi + ls_hi;
        m_lo = mnew_lo; m_hi = mnew_hi;

        #pragma unroll
        for (int j = 0; j < 8; j++) {
            o[j][0] *= corr_lo; o[j][1] *= corr_lo;
            o[j][2] *= corr_hi; o[j][3] *= corr_hi;
        }

        // ---- PV: O += Ph*Vh + Pl*Vh + Ph*Vl
        #pragma unroll
        for (int t = 0; t < 4; t++) {
            uint32_t ah[4], al[4];
            bsplit2(s[2 * t][0],     s[2 * t][1],     ah[0], al[0]);
            bsplit2(s[2 * t][2],     s[2 * t][3],     ah[1], al[1]);
            bsplit2(s[2 * t + 1][0], s[2 * t + 1][1], ah[2], al[2]);
            bsplit2(s[2 * t + 1][2], s[2 * t + 1][3], ah[3], al[3]);
            const int vrow = t * 16 + vlr;
            #pragma unroll
            for (int ndp = 0; ndp < 4; ndp++) {
                const uint32_t off = (uint32_t)(vrow * 128 + (((ndp * 2 + vck) ^ (vrow & 7)) * 16));
                uint32_t vh0, vh1, vh2, vh3, vl0, vl1, vl2, vl3;
                LDSM_X4_T(vh0, vh1, vh2, vh3, vbh + off);
                LDSM_X4_T(vl0, vl1, vl2, vl3, vbl + off);
                MMA_BF16(o[2 * ndp],     ah, vh0, vh1);
                MMA_BF16(o[2 * ndp],     al, vh0, vh1);
                MMA_BF16(o[2 * ndp],     ah, vl0, vl1);
                MMA_BF16(o[2 * ndp + 1], ah, vh2, vh3);
                MMA_BF16(o[2 * ndp + 1], al, vh2, vh3);
                MMA_BF16(o[2 * ndp + 1], ah, vl2, vl3);
            }
        }
        __syncthreads();
    }

    // epilogue: normalize + pre-round to tf32 (feeds the final GEMM)
    const float inv_lo = 1.f / l_lo;
    const float inv_hi = 1.f / l_hi;
    float* base_lo = O + ((size_t)(b * S_) + rlo) * DM + h * DK;
    float* base_hi = O + ((size_t)(b * S_) + rhi) * DM + h * DK;
    #pragma unroll
    for (int j = 0; j < 8; j++) {
        const int d = j * 8 + cb;
        *(float2*)(base_lo + d) = make_float2(tf32_rna(o[j][0] * inv_lo),
                                              tf32_rna(o[j][1] * inv_lo));
        *(float2*)(base_hi + d) = make_float2(tf32_rna(o[j][2] * inv_hi),
                                              tf32_rna(o[j][3] * inv_hi));
    }
}

// ---------------------------------------------------------------------------
// Launch
// ---------------------------------------------------------------------------
#define GEMM_SMEM 65536

extern "C" void kernel_launch(void* const* d_in, const int* in_sizes, int n_in,
                              void* d_out, int out_size)
{
    const float* x  = (const float*)d_in[0];
    const int*   am = (const int*)d_in[1];
    const float* wq = (const float*)d_in[2];
    const float* bq = (const float*)d_in[3];
    const float* wk = (const float*)d_in[4];
    const float* bk = (const float*)d_in[5];
    const float* wv = (const float*)d_in[6];
    const float* bv = (const float*)d_in[7];
    const float* wo = (const float*)d_in[8];
    const float* bo = (const float*)d_in[9];
    float* out = (float*)d_out;

    float *ap, *xc, *wc;
    __nv_bfloat16 *qh, *ql, *kh, *kl, *vh, *vl;
    cudaGetSymbolAddress((void**)&ap, g_att);
    cudaGetSymbolAddress((void**)&xc, g_xc);
    cudaGetSymbolAddress((void**)&wc, g_wc);
    cudaGetSymbolAddress((void**)&qh, g_qh);
    cudaGetSymbolAddress((void**)&ql, g_ql);
    cudaGetSymbolAddress((void**)&kh, g_kh);
    cudaGetSymbolAddress((void**)&kl, g_kl);
    cudaGetSymbolAddress((void**)&vh, g_vh);
    cudaGetSymbolAddress((void**)&vl, g_vl);
    float* wqc = wc;
    float* wkc = wc + DM * DM;
    float* wvc = wc + 2 * DM * DM;
    float* woc = wc + 3 * DM * DM;

    cudaFuncSetAttribute(gemm_tc_kernel,
                         cudaFuncAttributeMaxDynamicSharedMemorySize, GEMM_SMEM);
    cudaFuncSetAttribute(flash_attn_tc,
                         cudaFuncAttributeMaxDynamicSharedMemorySize, FA_SMEM);

    // pre-round x and weights to tf32 (rna)
    tf32_round_kernel<<<592, 256>>>((const float4*)x,  (float4*)xc,  MTOT * DM / 4);
    tf32_round_kernel<<<592, 256>>>((const float4*)wq, (float4*)wqc, DM * DM / 4);
    tf32_round_kernel<<<592, 256>>>((const float4*)wk, (float4*)wkc, DM * DM / 4);
    tf32_round_kernel<<<592, 256>>>((const float4*)wv, (float4*)wvc, DM * DM / 4);
    tf32_round_kernel<<<592, 256>>>((const float4*)wo, (float4*)woc, DM * DM / 4);

    dim3 ggrid(DM / 128, MTOT / 128);   // (8, 32)
    gemm_tc_kernel<<<ggrid, 256, GEMM_SMEM>>>(xc, wqc, bq, nullptr, qh, ql, 0);
    gemm_tc_kernel<<<ggrid, 256, GEMM_SMEM>>>(xc, wkc, bk, nullptr, kh, kl, 0);
    gemm_tc_kernel<<<ggrid, 256, GEMM_SMEM>>>(xc, wvc, bv, nullptr, vh, vl, 0);

    dim3 agrid(S_ / 64, H_, B_);        // (32, 16, 2)
    flash_attn_tc<<<agrid, 128, FA_SMEM>>>(qh, ql, kh, kl, vh, vl, am, ap);

    gemm_tc_kernel<<<ggrid, 256, GEMM_SMEM>>>(ap, woc, bo, out, nullptr, nullptr, 1);
}

// round 8
// speedup vs baseline: 7.0596x; 1.0378x over previous
#include <cuda_runtime.h>
#include <cuda_bf16.h>
#include <math.h>
#include <cstdint>

// Problem constants
#define B_   2
#define S_   2048
#define DM   1024
#define H_   16
#define DK   64
#define MTOT (B_ * S_)   // 4096

// Scratch (device globals)
__device__ float g_att[MTOT * DM];                  // [B*S, DM] (tf32-rounded)
__device__ float g_xc[MTOT * DM];                   // x pre-rounded to tf32
__device__ float g_wc[4 * DM * DM];                 // w_q,w_k,w_v,w_o pre-rounded
__device__ __nv_bfloat16 g_qh[B_ * H_ * S_ * DK];   // [B,H,S,DK] bf16 planes
__device__ __nv_bfloat16 g_ql[B_ * H_ * S_ * DK];
__device__ __nv_bfloat16 g_kh[B_ * H_ * S_ * DK];
__device__ __nv_bfloat16 g_kl[B_ * H_ * S_ * DK];
__device__ __nv_bfloat16 g_vh[B_ * H_ * S_ * DK];
__device__ __nv_bfloat16 g_vl[B_ * H_ * S_ * DK];

__device__ __forceinline__ uint32_t smem_u32(const void* p) {
    uint32_t a;
    asm("{ .reg .u64 t; cvta.to.shared.u64 t, %1; cvt.u32.u64 %0, t; }"
        : "=r"(a) : "l"(p));
    return a;
}

#define CP_ASYNC16(dst, src) \
    asm volatile("cp.async.cg.shared.global [%0], [%1], 16;" :: "r"(dst), "l"(src))
#define CP_ASYNC4(dst, src) \
    asm volatile("cp.async.ca.shared.global [%0], [%1], 4;" :: "r"(dst), "l"(src))
#define CP_COMMIT() asm volatile("cp.async.commit_group;" ::: "memory")
#define CP_WAIT1()  asm volatile("cp.async.wait_group 1;" ::: "memory")
#define CP_WAIT0()  asm volatile("cp.async.wait_group 0;" ::: "memory")

__device__ __forceinline__ float tf32_rna(float x) {
    uint32_t u;
    asm("cvt.rna.tf32.f32 %0, %1;" : "=r"(u) : "f"(x));
    return __uint_as_float(u);
}

#define LDSM_X4(r0, r1, r2, r3, addr) \
    asm volatile("ldmatrix.sync.aligned.m8n8.x4.shared.b16 {%0,%1,%2,%3}, [%4];" \
                 : "=r"(r0), "=r"(r1), "=r"(r2), "=r"(r3) : "r"(addr))

#define LDSM_X4_T(r0, r1, r2, r3, addr) \
    asm volatile("ldmatrix.sync.aligned.m8n8.x4.trans.shared.b16 {%0,%1,%2,%3}, [%4];" \
                 : "=r"(r0), "=r"(r1), "=r"(r2), "=r"(r3) : "r"(addr))

#define MMA_TF32(c, a, b) \
    asm volatile("mma.sync.aligned.m16n8k8.row.col.f32.tf32.tf32.f32 " \
                 "{%0,%1,%2,%3}, {%4,%5,%6,%7}, {%8,%9}, {%0,%1,%2,%3};" \
                 : "+f"((c)[0]), "+f"((c)[1]), "+f"((c)[2]), "+f"((c)[3]) \
                 : "r"((a)[0]), "r"((a)[1]), "r"((a)[2]), "r"((a)[3]), \
                   "r"((b)[0]), "r"((b)[1]))

#define MMA_BF16(c, a, b0, b1) \
    asm volatile("mma.sync.aligned.m16n8k16.row.col.f32.bf16.bf16.f32 " \
                 "{%0,%1,%2,%3}, {%4,%5,%6,%7}, {%8,%9}, {%0,%1,%2,%3};" \
                 : "+f"((c)[0]), "+f"((c)[1]), "+f"((c)[2]), "+f"((c)[3]) \
                 : "r"((a)[0]), "r"((a)[1]), "r"((a)[2]), "r"((a)[3]), \
                   "r"(b0), "r"(b1))

__device__ __forceinline__ void bsplit2(float x, float y, uint32_t& hi, uint32_t& lo) {
    __nv_bfloat162 h2, l2;
    h2.x = __float2bfloat16_rn(x);
    h2.y = __float2bfloat16_rn(y);
    l2.x = __float2bfloat16_rn(x - __bfloat162float(h2.x));
    l2.y = __float2bfloat16_rn(y - __bfloat162float(h2.y));
    hi = *reinterpret_cast<uint32_t*>(&h2);
    lo = *reinterpret_cast<uint32_t*>(&l2);
}

// ===========================================================================
// Fused tf32 pre-round: x + all 4 weights in one launch.
// ===========================================================================
__global__ void tf32_round_all(
    const float4* __restrict__ x,
    const float4* __restrict__ w0, const float4* __restrict__ w1,
    const float4* __restrict__ w2, const float4* __restrict__ w3,
    float4* __restrict__ xc, float4* __restrict__ wc)
{
    const int NX = MTOT * DM / 4;
    const int NW = DM * DM / 4;
    const int total = NX + 4 * NW;
    for (int i = blockIdx.x * blockDim.x + threadIdx.x; i < total;
         i += gridDim.x * blockDim.x) {
        float4 v;
        float4* dst;
        if (i < NX) {
            v = x[i]; dst = xc + i;
        } else {
            const int j = i - NX;
            const int r = j / NW, off = j - r * NW;
            const float4* src = (r == 0) ? w0 : (r == 1) ? w1 : (r == 2) ? w2 : w3;
            v = src[off]; dst = wc + j;
        }
        v.x = tf32_rna(v.x); v.y = tf32_rna(v.y);
        v.z = tf32_rna(v.z); v.w = tf32_rna(v.w);
        *dst = v;
    }
}

// ===========================================================================
// Fused QKV GEMM (NT), tf32 tensor core. grid (24, 32): bx>>3 selects weight.
// Writes Q,K,V all as bf16 hi/lo planes, permuted to [B,H,S,DK].
// ===========================================================================
__global__ void __launch_bounds__(256, 1) gemm_qkv_kernel(
    const float* __restrict__ A, const float* __restrict__ Wc,
    const float* __restrict__ bq, const float* __restrict__ bk,
    const float* __restrict__ bv,
    __nv_bfloat16* __restrict__ qh, __nv_bfloat16* __restrict__ ql,
    __nv_bfloat16* __restrict__ kh, __nv_bfloat16* __restrict__ kl,
    __nv_bfloat16* __restrict__ vh, __nv_bfloat16* __restrict__ vl)
{
    extern __shared__ char smem[];
    const uint32_t sbase = smem_u32(smem);
    const int tid = threadIdx.x;
    const int lane = tid & 31;
    const int wid = tid >> 5;
    const int wm = wid >> 2;
    const int wn = wid & 3;
    const int widx = blockIdx.x >> 3;
    const int n0 = (blockIdx.x & 7) * 128;
    const int m0 = blockIdx.y * 128;
    const float* W = Wc + (size_t)widx * DM * DM;
    const float* bias = (widx == 0) ? bq : (widx == 1) ? bk : bv;
    __nv_bfloat16* Chi = (widx == 0) ? qh : (widx == 1) ? kh : vh;
    __nv_bfloat16* Clo = (widx == 0) ? ql : (widx == 1) ? kl : vl;

    int lrow[4], lkg[4];
    uint32_t ldst[4];
    #pragma unroll
    for (int it = 0; it < 4; it++) {
        const int c = tid + it * 256;
        const int r = c >> 3, kg = c & 7;
        lrow[it] = r; lkg[it] = kg;
        ldst[it] = (uint32_t)(r * 128 + ((kg ^ (r & 7)) * 16));
    }

    const int lrA = (lane & 7) + ((lane >> 3) & 1) * 8;
    const int lkA = lane >> 4;
    const int lrB = (lane & 7) + (lane >> 4) * 8;
    const int lkB = (lane >> 3) & 1;

    float acc[4][4][4];
    #pragma unroll
    for (int i = 0; i < 4; i++)
        #pragma unroll
        for (int j = 0; j < 4; j++)
            #pragma unroll
            for (int r = 0; r < 4; r++) acc[i][j][r] = 0.f;

    auto load_tiles = [&](int buf, int k0) {
        const uint32_t ab = sbase + buf * 32768u;
        const uint32_t bb = ab + 16384u;
        #pragma unroll
        for (int it = 0; it < 4; it++) {
            const float* ga = A + (size_t)(m0 + lrow[it]) * 1024 + k0 + lkg[it] * 4;
            const float* gb = W + (size_t)(n0 + lrow[it]) * 1024 + k0 + lkg[it] * 4;
            CP_ASYNC16(ab + ldst[it], ga);
            CP_ASYNC16(bb + ldst[it], gb);
        }
    };

    auto compute = [&](int buf) {
        const uint32_t ab = sbase + buf * 32768u;
        const uint32_t bb = ab + 16384u;
        #pragma unroll
        for (int ks = 0; ks < 4; ks++) {
            uint32_t a[4][4];
            #pragma unroll
            for (int mt = 0; mt < 4; mt++) {
                const uint32_t addr = ab +
                    (uint32_t)((wm * 64 + mt * 16 + lrA) * 128 +
                               (((ks * 2 + lkA) ^ (lrA & 7)) * 16));
                LDSM_X4(a[mt][0], a[mt][1], a[mt][2], a[mt][3], addr);
            }
            uint32_t b[4][2];
            #pragma unroll
            for (int np = 0; np < 2; np++) {
                const uint32_t addr = bb +
                    (uint32_t)((wn * 32 + np * 16 + lrB) * 128 +
                               (((ks * 2 + lkB) ^ (lrB & 7)) * 16));
                LDSM_X4(b[np * 2][0], b[np * 2][1], b[np * 2 + 1][0], b[np * 2 + 1][1], addr);
            }
            #pragma unroll
            for (int mt = 0; mt < 4; mt++)
                #pragma unroll
                for (int nt = 0; nt < 4; nt++)
                    MMA_TF32(acc[mt][nt], a[mt], b[nt]);
        }
    };

    load_tiles(0, 0);  CP_COMMIT();
    load_tiles(1, 32); CP_COMMIT();
    for (int i = 0; i < 32; i++) {
        CP_WAIT1();
        __syncthreads();
        compute(i & 1);
        __syncthreads();
        if (i + 2 < 32) load_tiles(i & 1, (i + 2) * 32);
        CP_COMMIT();
    }

    const int lr = lane >> 2;
    const int lc = (lane & 3) * 2;
    #pragma unroll
    for (int mt = 0; mt < 4; mt++) {
        const int m = m0 + wm * 64 + mt * 16 + lr;
        #pragma unroll
        for (int nt = 0; nt < 4; nt++) {
            const int n = n0 + wn * 32 + nt * 8 + lc;
            const float b0 = __ldg(bias + n);
            const float b1 = __ldg(bias + n + 1);
            const float v00 = acc[mt][nt][0] + b0, v01 = acc[mt][nt][1] + b1;
            const float v10 = acc[mt][nt][2] + b0, v11 = acc[mt][nt][3] + b1;
            const int bb = m >> 11;
            const int s  = m & 2047;
            const int h  = n >> 6;
            const int d  = n & 63;
            const size_t i0 = (((size_t)(bb * H_ + h) * S_) + s) * DK + d;
            uint32_t h0, l0, h1, l1;
            bsplit2(v00, v01, h0, l0);
            bsplit2(v10, v11, h1, l1);
            *reinterpret_cast<uint32_t*>(Chi + i0) = h0;
            *reinterpret_cast<uint32_t*>(Clo + i0) = l0;
            *reinterpret_cast<uint32_t*>(Chi + i0 + 8 * DK) = h1;
            *reinterpret_cast<uint32_t*>(Clo + i0 + 8 * DK) = l1;
        }
    }
}

// ===========================================================================
// Output GEMM (NT), tf32: C[m,n] = A[m,k]*W[n,k] + bias[n], fp32 out.
// ===========================================================================
__global__ void __launch_bounds__(256, 1) gemm_out_kernel(
    const float* __restrict__ A, const float* __restrict__ W,
    const float* __restrict__ bias, float* __restrict__ C)
{
    extern __shared__ char smem[];
    const uint32_t sbase = smem_u32(smem);
    const int tid = threadIdx.x;
    const int lane = tid & 31;
    const int wid = tid >> 5;
    const int wm = wid >> 2;
    const int wn = wid & 3;
    const int m0 = blockIdx.y * 128;
    const int n0 = blockIdx.x * 128;

    int lrow[4], lkg[4];
    uint32_t ldst[4];
    #pragma unroll
    for (int it = 0; it < 4; it++) {
        const int c = tid + it * 256;
        const int r = c >> 3, kg = c & 7;
        lrow[it] = r; lkg[it] = kg;
        ldst[it] = (uint32_t)(r * 128 + ((kg ^ (r & 7)) * 16));
    }

    const int lrA = (lane & 7) + ((lane >> 3) & 1) * 8;
    const int lkA = lane >> 4;
    const int lrB = (lane & 7) + (lane >> 4) * 8;
    const int lkB = (lane >> 3) & 1;

    float acc[4][4][4];
    #pragma unroll
    for (int i = 0; i < 4; i++)
        #pragma unroll
        for (int j = 0; j < 4; j++)
            #pragma unroll
            for (int r = 0; r < 4; r++) acc[i][j][r] = 0.f;

    auto load_tiles = [&](int buf, int k0) {
        const uint32_t ab = sbase + buf * 32768u;
        const uint32_t bb = ab + 16384u;
        #pragma unroll
        for (int it = 0; it < 4; it++) {
            const float* ga = A + (size_t)(m0 + lrow[it]) * 1024 + k0 + lkg[it] * 4;
            const float* gb = W + (size_t)(n0 + lrow[it]) * 1024 + k0 + lkg[it] * 4;
            CP_ASYNC16(ab + ldst[it], ga);
            CP_ASYNC16(bb + ldst[it], gb);
        }
    };

    auto compute = [&](int buf) {
        const uint32_t ab = sbase + buf * 32768u;
        const uint32_t bb = ab + 16384u;
        #pragma unroll
        for (int ks = 0; ks < 4; ks++) {
            uint32_t a[4][4];
            #pragma unroll
            for (int mt = 0; mt < 4; mt++) {
                const uint32_t addr = ab +
                    (uint32_t)((wm * 64 + mt * 16 + lrA) * 128 +
                               (((ks * 2 + lkA) ^ (lrA & 7)) * 16));
                LDSM_X4(a[mt][0], a[mt][1], a[mt][2], a[mt][3], addr);
            }
            uint32_t b[4][2];
            #pragma unroll
            for (int np = 0; np < 2; np++) {
                const uint32_t addr = bb +
                    (uint32_t)((wn * 32 + np * 16 + lrB) * 128 +
                               (((ks * 2 + lkB) ^ (lrB & 7)) * 16));
                LDSM_X4(b[np * 2][0], b[np * 2][1], b[np * 2 + 1][0], b[np * 2 + 1][1], addr);
            }
            #pragma unroll
            for (int mt = 0; mt < 4; mt++)
                #pragma unroll
                for (int nt = 0; nt < 4; nt++)
                    MMA_TF32(acc[mt][nt], a[mt], b[nt]);
        }
    };

    load_tiles(0, 0);  CP_COMMIT();
    load_tiles(1, 32); CP_COMMIT();
    for (int i = 0; i < 32; i++) {
        CP_WAIT1();
        __syncthreads();
        compute(i & 1);
        __syncthreads();
        if (i + 2 < 32) load_tiles(i & 1, (i + 2) * 32);
        CP_COMMIT();
    }

    const int lr = lane >> 2;
    const int lc = (lane & 3) * 2;
    #pragma unroll
    for (int mt = 0; mt < 4; mt++) {
        const int m = m0 + wm * 64 + mt * 16 + lr;
        #pragma unroll
        for (int nt = 0; nt < 4; nt++) {
            const int n = n0 + wn * 32 + nt * 8 + lc;
            const float b0 = __ldg(bias + n);
            const float b1 = __ldg(bias + n + 1);
            float* p0 = C + (size_t)m * DM + n;
            *(float2*)p0 = make_float2(acc[mt][nt][0] + b0, acc[mt][nt][1] + b1);
            *(float2*)(p0 + 8 * DM) = make_float2(acc[mt][nt][2] + b0, acc[mt][nt][3] + b1);
        }
    }
}

// ===========================================================================
// Tensor-core flash attention, bf16 split-3 (QK and PV), double-buffered.
// Grid (S/64, H, B), 128 threads (4 warps x 16 q-rows).
// ===========================================================================
#define FA_QH  0
#define FA_QL  8192
#define FA_BUF 16384                  // + buf*32768 : KH, KL, VH, VL (8KB each)
#define FA_MSK 81920                  // + buf*256
#define FA_SMEM (81920 + 512)

__global__ void __launch_bounds__(128) flash_attn_tc(
    const __nv_bfloat16* __restrict__ Qh, const __nv_bfloat16* __restrict__ Ql,
    const __nv_bfloat16* __restrict__ Kh, const __nv_bfloat16* __restrict__ Kl,
    const __nv_bfloat16* __restrict__ Vh, const __nv_bfloat16* __restrict__ Vl,
    const int* __restrict__ amask, float* __restrict__ O)
{
    extern __shared__ char fs[];
    const uint32_t sbase = smem_u32(fs);
    const int b = blockIdx.z;
    const int h = blockIdx.y;
    const int q0 = (gridDim.x - 1 - blockIdx.x) * 64;   // heavy tiles first
    const int tid = threadIdx.x;
    const int lane = tid & 31;
    const int wid = tid >> 5;
    const size_t hb = ((size_t)(b * H_ + h)) * S_ * DK;

    auto load_kv = [&](int buf, int k0) {
        const uint32_t base = sbase + FA_BUF + buf * 32768u;
        #pragma unroll
        for (int it = 0; it < 4; it++) {
            const int c = tid + it * 128;
            const int r = c >> 3, kg = c & 7;
            const uint32_t sw = (uint32_t)(r * 128 + ((kg ^ (r & 7)) * 16));
            const size_t g = hb + (size_t)(k0 + r) * DK + kg * 8;
            CP_ASYNC16(base + sw,          Kh + g);
            CP_ASYNC16(base + 8192 + sw,   Kl + g);
            CP_ASYNC16(base + 16384 + sw,  Vh + g);
            CP_ASYNC16(base + 24576 + sw,  Vl + g);
        }
        if (tid < 64)
            CP_ASYNC4(sbase + FA_MSK + buf * 256u + tid * 4,
                      amask + b * S_ + k0 + tid);
    };

    // Q tile load (swizzled, one-time)
    #pragma unroll
    for (int it = 0; it < 4; it++) {
        const int idx = tid + it * 128;
        const int r = idx >> 3, c = idx & 7;
        const uint32_t sw = (uint32_t)(r * 128 + ((c ^ (r & 7)) * 16));
        const size_t g = hb + (size_t)(q0 + r) * DK + c * 8;
        *(uint4*)(fs + FA_QH + sw) = *(const uint4*)(Qh + g);
        *(uint4*)(fs + FA_QL + sw) = *(const uint4*)(Ql + g);
    }
    load_kv(0, 0);
    CP_COMMIT();
    __syncthreads();

    // Q fragments
    const int lrA = (lane & 7) + ((lane >> 3) & 1) * 8;
    const int lkA = lane >> 4;
    uint32_t qfh[4][4], qfl[4][4];
    {
        const uint32_t qbh = sbase + FA_QH;
        const uint32_t qbl = sbase + FA_QL;
        const int row = wid * 16 + lrA;
        #pragma unroll
        for (int ks = 0; ks < 4; ks++) {
            const uint32_t off = (uint32_t)(row * 128 + (((ks * 2 + lkA) ^ (row & 7)) * 16));
            LDSM_X4(qfh[ks][0], qfh[ks][1], qfh[ks][2], qfh[ks][3], qbh + off);
            LDSM_X4(qfl[ks][0], qfl[ks][1], qfl[ks][2], qfl[ks][3], qbl + off);
        }
    }

    const int rlo = q0 + wid * 16 + (lane >> 2);
    const int rhi = rlo + 8;
    const int cb = (lane & 3) * 2;
    const int lrB = (lane & 7) + ((lane >> 4) & 1) * 8;
    const int lkB = (lane >> 3) & 1;
    const int vlr = (lane & 7) + ((lane >> 3) & 1) * 8;
    const int vck = lane >> 4;

    float o[8][4];
    #pragma unroll
    for (int j = 0; j < 8; j++)
        #pragma unroll
        for (int r = 0; r < 4; r++) o[j][r] = 0.f;
    float m_lo = -1e30f, m_hi = -1e30f, l_lo = 0.f, l_hi = 0.f;

    const int ntiles = q0 / 64 + 1;
    for (int i = 0; i < ntiles; i++) {
        const int k0 = i * 64;
        const int buf = i & 1;
        if (i + 1 < ntiles) {
            load_kv((i + 1) & 1, k0 + 64);
            CP_COMMIT();
            CP_WAIT1();
        } else {
            CP_WAIT0();
        }
        __syncthreads();

        const int* smask = (const int*)(fs + FA_MSK + buf * 256);
        const uint32_t kbh = sbase + FA_BUF + buf * 32768u;
        const uint32_t kbl = kbh + 8192u;
        const uint32_t vbh = kbh + 16384u;
        const uint32_t vbl = kbh + 24576u;

        // ---- scores: S = Qh*Kh + Qh*Kl + Ql*Kh
        float s[8][4];
        #pragma unroll
        for (int j = 0; j < 8; j++)
            #pragma unroll
            for (int r = 0; r < 4; r++) s[j][r] = 0.f;

        #pragma unroll
        for (int jp = 0; jp < 4; jp++) {
            const int rowb = jp * 16 + lrB;
            #pragma unroll
            for (int ks = 0; ks < 4; ks++) {
                const uint32_t off = (uint32_t)(rowb * 128 + (((ks * 2 + lkB) ^ (rowb & 7)) * 16));
                uint32_t bh0, bh1, bh2, bh3, bl0, bl1, bl2, bl3;
                LDSM_X4(bh0, bh1, bh2, bh3, kbh + off);
                LDSM_X4(bl0, bl1, bl2, bl3, kbl + off);
                MMA_BF16(s[2 * jp],     qfh[ks], bh0, bh1);
                MMA_BF16(s[2 * jp],     qfh[ks], bl0, bl1);
                MMA_BF16(s[2 * jp],     qfl[ks], bh0, bh1);
                MMA_BF16(s[2 * jp + 1], qfh[ks], bh2, bh3);
                MMA_BF16(s[2 * jp + 1], qfh[ks], bl2, bl3);
                MMA_BF16(s[2 * jp + 1], qfl[ks], bh2, bh3);
            }
        }

        // ---- mask + online softmax
        float mloc_lo = -1e30f, mloc_hi = -1e30f;
        #pragma unroll
        for (int j = 0; j < 8; j++) {
            const int c0 = k0 + j * 8 + cb;
            const int c1 = c0 + 1;
            const bool mv0 = smask[j * 8 + cb] != 0;
            const bool mv1 = smask[j * 8 + cb + 1] != 0;
            s[j][0] = (mv0 && c0 <= rlo) ? s[j][0] * 0.125f : -1e30f;
            s[j][1] = (mv1 && c1 <= rlo) ? s[j][1] * 0.125f : -1e30f;
            s[j][2] = (mv0 && c0 <= rhi) ? s[j][2] * 0.125f : -1e30f;
            s[j][3] = (mv1 && c1 <= rhi) ? s[j][3] * 0.125f : -1e30f;
            mloc_lo = fmaxf(mloc_lo, fmaxf(s[j][0], s[j][1]));
            mloc_hi = fmaxf(mloc_hi, fmaxf(s[j][2], s[j][3]));
        }
        mloc_lo = fmaxf(mloc_lo, __shfl_xor_sync(0xFFFFFFFFu, mloc_lo, 1));
        mloc_lo = fmaxf(mloc_lo, __shfl_xor_sync(0xFFFFFFFFu, mloc_lo, 2));
        mloc_hi = fmaxf(mloc_hi, __shfl_xor_sync(0xFFFFFFFFu, mloc_hi, 1));
        mloc_hi = fmaxf(mloc_hi, __shfl_xor_sync(0xFFFFFFFFu, mloc_hi, 2));

        const float mnew_lo = fmaxf(m_lo, mloc_lo);
        const float mnew_hi = fmaxf(m_hi, mloc_hi);
        const float corr_lo = __expf(m_lo - mnew_lo);
        const float corr_hi = __expf(m_hi - mnew_hi);

        float ls_lo = 0.f, ls_hi = 0.f;
        #pragma unroll
        for (int j = 0; j < 8; j++) {
            s[j][0] = __expf(s[j][0] - mnew_lo);
            s[j][1] = __expf(s[j][1] - mnew_lo);
            s[j][2] = __expf(s[j][2] - mnew_hi);
            s[j][3] = __expf(s[j][3] - mnew_hi);
            ls_lo += s[j][0] + s[j][1];
            ls_hi += s[j][2] + s[j][3];
        }
        ls_lo += __shfl_xor_sync(0xFFFFFFFFu, ls_lo, 1);
        ls_lo += __shfl_xor_sync(0xFFFFFFFFu, ls_lo, 2);
        ls_hi += __shfl_xor_sync(0xFFFFFFFFu, ls_hi, 1);
        ls_hi += __shfl_xor_sync(0xFFFFFFFFu, ls_hi, 2);

        l_lo = l_lo * corr_lo + ls_lo;
        l_hi = l_hi * corr_hi + ls_hi;
        m_lo = mnew_lo; m_hi = mnew_hi;

        #pragma unroll
        for (int j = 0; j < 8; j++) {
            o[j][0] *= corr_lo; o[j][1] *= corr_lo;
            o[j][2] *= corr_hi; o[j][3] *= corr_hi;
        }

        // ---- PV: O += Ph*Vh + Pl*Vh + Ph*Vl
        #pragma unroll
        for (int t = 0; t < 4; t++) {
            uint32_t ah[4], al[4];
            bsplit2(s[2 * t][0],     s[2 * t][1],     ah[0], al[0]);
            bsplit2(s[2 * t][2],     s[2 * t][3],     ah[1], al[1]);
            bsplit2(s[2 * t + 1][0], s[2 * t + 1][1], ah[2], al[2]);
            bsplit2(s[2 * t + 1][2], s[2 * t + 1][3], ah[3], al[3]);
            const int vrow = t * 16 + vlr;
            #pragma unroll
            for (int ndp = 0; ndp < 4; ndp++) {
                const uint32_t off = (uint32_t)(vrow * 128 + (((ndp * 2 + vck) ^ (vrow & 7)) * 16));
                uint32_t vh0, vh1, vh2, vh3, vl0, vl1, vl2, vl3;
                LDSM_X4_T(vh0, vh1, vh2, vh3, vbh + off);
                LDSM_X4_T(vl0, vl1, vl2, vl3, vbl + off);
                MMA_BF16(o[2 * ndp],     ah, vh0, vh1);
                MMA_BF16(o[2 * ndp],     al, vh0, vh1);
                MMA_BF16(o[2 * ndp],     ah, vl0, vl1);
                MMA_BF16(o[2 * ndp + 1], ah, vh2, vh3);
                MMA_BF16(o[2 * ndp + 1], al, vh2, vh3);
                MMA_BF16(o[2 * ndp + 1], ah, vl2, vl3);
            }
        }
        __syncthreads();
    }

    // epilogue: normalize + tf32 pre-round (feeds the output GEMM)
    const float inv_lo = 1.f / l_lo;
    const float inv_hi = 1.f / l_hi;
    float* base_lo = O + ((size_t)(b * S_) + rlo) * DM + h * DK;
    float* base_hi = O + ((size_t)(b * S_) + rhi) * DM + h * DK;
    #pragma unroll
    for (int j = 0; j < 8; j++) {
        const int d = j * 8 + cb;
        *(float2*)(base_lo + d) = make_float2(tf32_rna(o[j][0] * inv_lo),
                                              tf32_rna(o[j][1] * inv_lo));
        *(float2*)(base_hi + d) = make_float2(tf32_rna(o[j][2] * inv_hi),
                                              tf32_rna(o[j][3] * inv_hi));
    }
}

// ---------------------------------------------------------------------------
// Launch
// ---------------------------------------------------------------------------
#define GEMM_SMEM 65536

extern "C" void kernel_launch(void* const* d_in, const int* in_sizes, int n_in,
                              void* d_out, int out_size)
{
    const float* x  = (const float*)d_in[0];
    const int*   am = (const int*)d_in[1];
    const float* wq = (const float*)d_in[2];
    const float* bq = (const float*)d_in[3];
    const float* wk = (const float*)d_in[4];
    const float* bk = (const float*)d_in[5];
    const float* wv = (const float*)d_in[6];
    const float* bv = (const float*)d_in[7];
    const float* wo = (const float*)d_in[8];
    const float* bo = (const float*)d_in[9];
    float* out = (float*)d_out;

    float *ap, *xc, *wc;
    __nv_bfloat16 *qh, *ql, *kh, *kl, *vh, *vl;
    cudaGetSymbolAddress((void**)&ap, g_att);
    cudaGetSymbolAddress((void**)&xc, g_xc);
    cudaGetSymbolAddress((void**)&wc, g_wc);
    cudaGetSymbolAddress((void**)&qh, g_qh);
    cudaGetSymbolAddress((void**)&ql, g_ql);
    cudaGetSymbolAddress((void**)&kh, g_kh);
    cudaGetSymbolAddress((void**)&kl, g_kl);
    cudaGetSymbolAddress((void**)&vh, g_vh);
    cudaGetSymbolAddress((void**)&vl, g_vl);
    float* woc = wc + 3 * DM * DM;

    cudaFuncSetAttribute(gemm_qkv_kernel,
                         cudaFuncAttributeMaxDynamicSharedMemorySize, GEMM_SMEM);
    cudaFuncSetAttribute(gemm_out_kernel,
                         cudaFuncAttributeMaxDynamicSharedMemorySize, GEMM_SMEM);
    cudaFuncSetAttribute(flash_attn_tc,
                         cudaFuncAttributeMaxDynamicSharedMemorySize, FA_SMEM);

    // fused tf32 pre-round: x + 4 weights, one launch
    tf32_round_all<<<1184, 256>>>((const float4*)x,
                                  (const float4*)wq, (const float4*)wk,
                                  (const float4*)wv, (const float4*)wo,
                                  (float4*)xc, (float4*)wc);

    dim3 qkvgrid(24, 32);
    gemm_qkv_kernel<<<qkvgrid, 256, GEMM_SMEM>>>(xc, wc, bq, bk, bv,
                                                 qh, ql, kh, kl, vh, vl);

    dim3 agrid(S_ / 64, H_, B_);        // (32, 16, 2)
    flash_attn_tc<<<agrid, 128, FA_SMEM>>>(qh, ql, kh, kl, vh, vl, am, ap);

    dim3 ogrid(DM / 128, MTOT / 128);   // (8, 32)
    gemm_out_kernel<<<ogrid, 256, GEMM_SMEM>>>(ap, woc, bo, out);
}

// round 13
// speedup vs baseline: 7.7419x; 1.0966x over previous
#include <cuda_runtime.h>
#include <cuda_bf16.h>
#include <math.h>
#include <cstdint>

// Problem constants
#define B_   2
#define S_   2048
#define DM   1024
#define H_   16
#define DK   64
#define MTOT (B_ * S_)   // 4096

// Scratch (device globals)
__device__ float g_att[MTOT * DM];                  // [B*S, DM] (tf32-rounded)
__device__ float g_xc[MTOT * DM];                   // x pre-rounded to tf32
__device__ float g_wc[4 * DM * DM];                 // w_q,w_k,w_v,w_o pre-rounded
__device__ __nv_bfloat16 g_qh[B_ * H_ * S_ * DK];   // [B,H,S,DK] bf16 planes
__device__ __nv_bfloat16 g_ql[B_ * H_ * S_ * DK];
__device__ __nv_bfloat16 g_kh[B_ * H_ * S_ * DK];
__device__ __nv_bfloat16 g_kl[B_ * H_ * S_ * DK];
__device__ __nv_bfloat16 g_vh[B_ * H_ * S_ * DK];
__device__ __nv_bfloat16 g_vl[B_ * H_ * S_ * DK];

__device__ __forceinline__ uint32_t smem_u32(const void* p) {
    uint32_t a;
    asm("{ .reg .u64 t; cvta.to.shared.u64 t, %1; cvt.u32.u64 %0, t; }"
        : "=r"(a) : "l"(p));
    return a;
}

#define CP_ASYNC16(dst, src) \
    asm volatile("cp.async.cg.shared.global [%0], [%1], 16;" :: "r"(dst), "l"(src))
#define CP_ASYNC4(dst, src) \
    asm volatile("cp.async.ca.shared.global [%0], [%1], 4;" :: "r"(dst), "l"(src))
#define CP_COMMIT() asm volatile("cp.async.commit_group;" ::: "memory")
#define CP_WAIT1()  asm volatile("cp.async.wait_group 1;" ::: "memory")
#define CP_WAIT0()  asm volatile("cp.async.wait_group 0;" ::: "memory")

__device__ __forceinline__ float tf32_rna(float x) {
    uint32_t u;
    asm("cvt.rna.tf32.f32 %0, %1;" : "=r"(u) : "f"(x));
    return __uint_as_float(u);
}

#define LDSM_X4(r0, r1, r2, r3, addr) \
    asm volatile("ldmatrix.sync.aligned.m8n8.x4.shared.b16 {%0,%1,%2,%3}, [%4];" \
                 : "=r"(r0), "=r"(r1), "=r"(r2), "=r"(r3) : "r"(addr))

#define LDSM_X4_T(r0, r1, r2, r3, addr) \
    asm volatile("ldmatrix.sync.aligned.m8n8.x4.trans.shared.b16 {%0,%1,%2,%3}, [%4];" \
                 : "=r"(r0), "=r"(r1), "=r"(r2), "=r"(r3) : "r"(addr))

#define MMA_TF32(c, a, b) \
    asm volatile("mma.sync.aligned.m16n8k8.row.col.f32.tf32.tf32.f32 " \
                 "{%0,%1,%2,%3}, {%4,%5,%6,%7}, {%8,%9}, {%0,%1,%2,%3};" \
                 : "+f"((c)[0]), "+f"((c)[1]), "+f"((c)[2]), "+f"((c)[3]) \
                 : "r"((a)[0]), "r"((a)[1]), "r"((a)[2]), "r"((a)[3]), \
                   "r"((b)[0]), "r"((b)[1]))

#define MMA_BF16(c, a, b0, b1) \
    asm volatile("mma.sync.aligned.m16n8k16.row.col.f32.bf16.bf16.f32 " \
                 "{%0,%1,%2,%3}, {%4,%5,%6,%7}, {%8,%9}, {%0,%1,%2,%3};" \
                 : "+f"((c)[0]), "+f"((c)[1]), "+f"((c)[2]), "+f"((c)[3]) \
                 : "r"((a)[0]), "r"((a)[1]), "r"((a)[2]), "r"((a)[3]), \
                   "r"(b0), "r"(b1))

__device__ __forceinline__ void bsplit2(float x, float y, uint32_t& hi, uint32_t& lo) {
    __nv_bfloat162 h2, l2;
    h2.x = __float2bfloat16_rn(x);
    h2.y = __float2bfloat16_rn(y);
    l2.x = __float2bfloat16_rn(x - __bfloat162float(h2.x));
    l2.y = __float2bfloat16_rn(y - __bfloat162float(h2.y));
    hi = *reinterpret_cast<uint32_t*>(&h2);
    lo = *reinterpret_cast<uint32_t*>(&l2);
}

// ===========================================================================
// Fused tf32 pre-round: x + all 4 weights in one launch.
// ===========================================================================
__global__ void tf32_round_all(
    const float4* __restrict__ x,
    const float4* __restrict__ w0, const float4* __restrict__ w1,
    const float4* __restrict__ w2, const float4* __restrict__ w3,
    float4* __restrict__ xc, float4* __restrict__ wc)
{
    const int NX = MTOT * DM / 4;
    const int NW = DM * DM / 4;
    const int total = NX + 4 * NW;
    for (int i = blockIdx.x * blockDim.x + threadIdx.x; i < total;
         i += gridDim.x * blockDim.x) {
        float4 v;
        float4* dst;
        if (i < NX) {
            v = x[i]; dst = xc + i;
        } else {
            const int j = i - NX;
            const int r = j / NW, off = j - r * NW;
            const float4* src = (r == 0) ? w0 : (r == 1) ? w1 : (r == 2) ? w2 : w3;
            v = src[off]; dst = wc + j;
        }
        v.x = tf32_rna(v.x); v.y = tf32_rna(v.y);
        v.z = tf32_rna(v.z); v.w = tf32_rna(v.w);
        *dst = v;
    }
}

// ===========================================================================
// Fused QKV GEMM (NT), tf32 tensor core. grid (24, 32): bx>>3 selects weight.
// __launch_bounds__(256, 2): cap regs at 128 -> 2 CTAs/SM (4 warps/SMSP).
// ===========================================================================
__global__ void __launch_bounds__(256, 2) gemm_qkv_kernel(
    const float* __restrict__ A, const float* __restrict__ Wc,
    const float* __restrict__ bq, const float* __restrict__ bk,
    const float* __restrict__ bv,
    __nv_bfloat16* __restrict__ qh, __nv_bfloat16* __restrict__ ql,
    __nv_bfloat16* __restrict__ kh, __nv_bfloat16* __restrict__ kl,
    __nv_bfloat16* __restrict__ vh, __nv_bfloat16* __restrict__ vl)
{
    extern __shared__ char smem[];
    const uint32_t sbase = smem_u32(smem);
    const int tid = threadIdx.x;
    const int lane = tid & 31;
    const int wid = tid >> 5;
    const int wm = wid >> 2;
    const int wn = wid & 3;
    const int widx = blockIdx.x >> 3;
    const int n0 = (blockIdx.x & 7) * 128;
    const int m0 = blockIdx.y * 128;
    const float* W = Wc + (size_t)widx * DM * DM;
    const float* bias = (widx == 0) ? bq : (widx == 1) ? bk : bv;
    __nv_bfloat16* Chi = (widx == 0) ? qh : (widx == 1) ? kh : vh;
    __nv_bfloat16* Clo = (widx == 0) ? ql : (widx == 1) ? kl : vl;

    int lrow[4], lkg[4];
    uint32_t ldst[4];
    #pragma unroll
    for (int it = 0; it < 4; it++) {
        const int c = tid + it * 256;
        const int r = c >> 3, kg = c & 7;
        lrow[it] = r; lkg[it] = kg;
        ldst[it] = (uint32_t)(r * 128 + ((kg ^ (r & 7)) * 16));
    }

    const int lrA = (lane & 7) + ((lane >> 3) & 1) * 8;
    const int lkA = lane >> 4;
    const int lrB = (lane & 7) + (lane >> 4) * 8;
    const int lkB = (lane >> 3) & 1;

    float acc[4][4][4];
    #pragma unroll
    for (int i = 0; i < 4; i++)
        #pragma unroll
        for (int j = 0; j < 4; j++)
            #pragma unroll
            for (int r = 0; r < 4; r++) acc[i][j][r] = 0.f;

    auto load_tiles = [&](int buf, int k0) {
        const uint32_t ab = sbase + buf * 32768u;
        const uint32_t bb = ab + 16384u;
        #pragma unroll
        for (int it = 0; it < 4; it++) {
            const float* ga = A + (size_t)(m0 + lrow[it]) * 1024 + k0 + lkg[it] * 4;
            const float* gb = W + (size_t)(n0 + lrow[it]) * 1024 + k0 + lkg[it] * 4;
            CP_ASYNC16(ab + ldst[it], ga);
            CP_ASYNC16(bb + ldst[it], gb);
        }
    };

    auto compute = [&](int buf) {
        const uint32_t ab = sbase + buf * 32768u;
        const uint32_t bb = ab + 16384u;
        #pragma unroll
        for (int ks = 0; ks < 4; ks++) {
            uint32_t a[4][4];
            #pragma unroll
            for (int mt = 0; mt < 4; mt++) {
                const uint32_t addr = ab +
                    (uint32_t)((wm * 64 + mt * 16 + lrA) * 128 +
                               (((ks * 2 + lkA) ^ (lrA & 7)) * 16));
                LDSM_X4(a[mt][0], a[mt][1], a[mt][2], a[mt][3], addr);
            }
            uint32_t b[4][2];
            #pragma unroll
            for (int np = 0; np < 2; np++) {
                const uint32_t addr = bb +
                    (uint32_t)((wn * 32 + np * 16 + lrB) * 128 +
                               (((ks * 2 + lkB) ^ (lrB & 7)) * 16));
                LDSM_X4(b[np * 2][0], b[np * 2][1], b[np * 2 + 1][0], b[np * 2 + 1][1], addr);
            }
            #pragma unroll
            for (int mt = 0; mt < 4; mt++)
                #pragma unroll
                for (int nt = 0; nt < 4; nt++)
                    MMA_TF32(acc[mt][nt], a[mt], b[nt]);
        }
    };

    load_tiles(0, 0);  CP_COMMIT();
    load_tiles(1, 32); CP_COMMIT();
    for (int i = 0; i < 32; i++) {
        CP_WAIT1();
        __syncthreads();
        compute(i & 1);
        __syncthreads();
        if (i + 2 < 32) load_tiles(i & 1, (i + 2) * 32);
        CP_COMMIT();
    }

    const int lr = lane >> 2;
    const int lc = (lane & 3) * 2;
    #pragma unroll
    for (int mt = 0; mt < 4; mt++) {
        const int m = m0 + wm * 64 + mt * 16 + lr;
        #pragma unroll
        for (int nt = 0; nt < 4; nt++) {
            const int n = n0 + wn * 32 + nt * 8 + lc;
            const float b0 = __ldg(bias + n);
            const float b1 = __ldg(bias + n + 1);
            const float v00 = acc[mt][nt][0] + b0, v01 = acc[mt][nt][1] + b1;
            const float v10 = acc[mt][nt][2] + b0, v11 = acc[mt][nt][3] + b1;
            const int bb = m >> 11;
            const int s  = m & 2047;
            const int h  = n >> 6;
            const int d  = n & 63;
            const size_t i0 = (((size_t)(bb * H_ + h) * S_) + s) * DK + d;
            uint32_t h0, l0, h1, l1;
            bsplit2(v00, v01, h0, l0);
            bsplit2(v10, v11, h1, l1);
            *reinterpret_cast<uint32_t*>(Chi + i0) = h0;
            *reinterpret_cast<uint32_t*>(Clo + i0) = l0;
            *reinterpret_cast<uint32_t*>(Chi + i0 + 8 * DK) = h1;
            *reinterpret_cast<uint32_t*>(Clo + i0 + 8 * DK) = l1;
        }
    }
}

// ===========================================================================
// Output GEMM (NT), tf32: C[m,n] = A[m,k]*W[n,k] + bias[n], fp32 out.
// __launch_bounds__(256, 2): cap regs at 128 -> 2 CTAs/SM.
// ===========================================================================
__global__ void __launch_bounds__(256, 2) gemm_out_kernel(
    const float* __restrict__ A, const float* __restrict__ W,
    const float* __restrict__ bias, float* __restrict__ C)
{
    extern __shared__ char smem[];
    const uint32_t sbase = smem_u32(smem);
    const int tid = threadIdx.x;
    const int lane = tid & 31;
    const int wid = tid >> 5;
    const int wm = wid >> 2;
    const int wn = wid & 3;
    const int m0 = blockIdx.y * 128;
    const int n0 = blockIdx.x * 128;

    int lrow[4], lkg[4];
    uint32_t ldst[4];
    #pragma unroll
    for (int it = 0; it < 4; it++) {
        const int c = tid + it * 256;
        const int r = c >> 3, kg = c & 7;
        lrow[it] = r; lkg[it] = kg;
        ldst[it] = (uint32_t)(r * 128 + ((kg ^ (r & 7)) * 16));
    }

    const int lrA = (lane & 7) + ((lane >> 3) & 1) * 8;
    const int lkA = lane >> 4;
    const int lrB = (lane & 7) + (lane >> 4) * 8;
    const int lkB = (lane >> 3) & 1;

    float acc[4][4][4];
    #pragma unroll
    for (int i = 0; i < 4; i++)
        #pragma unroll
        for (int j = 0; j < 4; j++)
            #pragma unroll
            for (int r = 0; r < 4; r++) acc[i][j][r] = 0.f;

    auto load_tiles = [&](int buf, int k0) {
        const uint32_t ab = sbase + buf * 32768u;
        const uint32_t bb = ab + 16384u;
        #pragma unroll
        for (int it = 0; it < 4; it++) {
            const float* ga = A + (size_t)(m0 + lrow[it]) * 1024 + k0 + lkg[it] * 4;
            const float* gb = W + (size_t)(n0 + lrow[it]) * 1024 + k0 + lkg[it] * 4;
            CP_ASYNC16(ab + ldst[it], ga);
            CP_ASYNC16(bb + ldst[it], gb);
        }
    };

    auto compute = [&](int buf) {
        const uint32_t ab = sbase + buf * 32768u;
        const uint32_t bb = ab + 16384u;
        #pragma unroll
        for (int ks = 0; ks < 4; ks++) {
            uint32_t a[4][4];
            #pragma unroll
            for (int mt = 0; mt < 4; mt++) {
                const uint32_t addr = ab +
                    (uint32_t)((wm * 64 + mt * 16 + lrA) * 128 +
                               (((ks * 2 + lkA) ^ (lrA & 7)) * 16));
                LDSM_X4(a[mt][0], a[mt][1], a[mt][2], a[mt][3], addr);
            }
            uint32_t b[4][2];
            #pragma unroll
            for (int np = 0; np < 2; np++) {
                const uint32_t addr = bb +
                    (uint32_t)((wn * 32 + np * 16 + lrB) * 128 +
                               (((ks * 2 + lkB) ^ (lrB & 7)) * 16));
                LDSM_X4(b[np * 2][0], b[np * 2][1], b[np * 2 + 1][0], b[np * 2 + 1][1], addr);
            }
            #pragma unroll
            for (int mt = 0; mt < 4; mt++)
                #pragma unroll
                for (int nt = 0; nt < 4; nt++)
                    MMA_TF32(acc[mt][nt], a[mt], b[nt]);
        }
    };

    load_tiles(0, 0);  CP_COMMIT();
    load_tiles(1, 32); CP_COMMIT();
    for (int i = 0; i < 32; i++) {
        CP_WAIT1();
        __syncthreads();
        compute(i & 1);
        __syncthreads();
        if (i + 2 < 32) load_tiles(i & 1, (i + 2) * 32);
        CP_COMMIT();
    }

    const int lr = lane >> 2;
    const int lc = (lane & 3) * 2;
    #pragma unroll
    for (int mt = 0; mt < 4; mt++) {
        const int m = m0 + wm * 64 + mt * 16 + lr;
        #pragma unroll
        for (int nt = 0; nt < 4; nt++) {
            const int n = n0 + wn * 32 + nt * 8 + lc;
            const float b0 = __ldg(bias + n);
            const float b1 = __ldg(bias + n + 1);
            float* p0 = C + (size_t)m * DM + n;
            *(float2*)p0 = make_float2(acc[mt][nt][0] + b0, acc[mt][nt][1] + b1);
            *(float2*)(p0 + 8 * DM) = make_float2(acc[mt][nt][2] + b0, acc[mt][nt][3] + b1);
        }
    }
}

// ===========================================================================
// Tensor-core flash attention, bf16 split-3 (QK and PV), double-buffered.
// Grid (S/64, H, B), 128 threads (4 warps x 16 q-rows).
// ===========================================================================
#define FA_QH  0
#define FA_QL  8192
#define FA_BUF 16384                  // + buf*32768 : KH, KL, VH, VL (8KB each)
#define FA_MSK 81920                  // + buf*256
#define FA_SMEM (81920 + 512)

__global__ void __launch_bounds__(128) flash_attn_tc(
    const __nv_bfloat16* __restrict__ Qh, const __nv_bfloat16* __restrict__ Ql,
    const __nv_bfloat16* __restrict__ Kh, const __nv_bfloat16* __restrict__ Kl,
    const __nv_bfloat16* __restrict__ Vh, const __nv_bfloat16* __restrict__ Vl,
    const int* __restrict__ amask, float* __restrict__ O)
{
    extern __shared__ char fs[];
    const uint32_t sbase = smem_u32(fs);
    const int b = blockIdx.z;
    const int h = blockIdx.y;
    const int q0 = (gridDim.x - 1 - blockIdx.x) * 64;   // heavy tiles first
    const int tid = threadIdx.x;
    const int lane = tid & 31;
    const int wid = tid >> 5;
    const size_t hb = ((size_t)(b * H_ + h)) * S_ * DK;

    auto load_kv = [&](int buf, int k0) {
        const uint32_t base = sbase + FA_BUF + buf * 32768u;
        #pragma unroll
        for (int it = 0; it < 4; it++) {
            const int c = tid + it * 128;
            const int r = c >> 3, kg = c & 7;
            const uint32_t sw = (uint32_t)(r * 128 + ((kg ^ (r & 7)) * 16));
            const size_t g = hb + (size_t)(k0 + r) * DK + kg * 8;
            CP_ASYNC16(base + sw,          Kh + g);
            CP_ASYNC16(base + 8192 + sw,   Kl + g);
            CP_ASYNC16(base + 16384 + sw,  Vh + g);
            CP_ASYNC16(base + 24576 + sw,  Vl + g);
        }
        if (tid < 64)
            CP_ASYNC4(sbase + FA_MSK + buf * 256u + tid * 4,
                      amask + b * S_ + k0 + tid);
    };

    // Q tile load (swizzled, one-time)
    #pragma unroll
    for (int it = 0; it < 4; it++) {
        const int idx = tid + it * 128;
        const int r = idx >> 3, c = idx & 7;
        const uint32_t sw = (uint32_t)(r * 128 + ((c ^ (r & 7)) * 16));
        const size_t g = hb + (size_t)(q0 + r) * DK + c * 8;
        *(uint4*)(fs + FA_QH + sw) = *(const uint4*)(Qh + g);
        *(uint4*)(fs + FA_QL + sw) = *(const uint4*)(Ql + g);
    }
    load_kv(0, 0);
    CP_COMMIT();
    __syncthreads();

    // Q fragments
    const int lrA = (lane & 7) + ((lane >> 3) & 1) * 8;
    const int lkA = lane >> 4;
    uint32_t qfh[4][4], qfl[4][4];
    {
        const uint32_t qbh = sbase + FA_QH;
        const uint32_t qbl = sbase + FA_QL;
        const int row = wid * 16 + lrA;
        #pragma unroll
        for (int ks = 0; ks < 4; ks++) {
            const uint32_t off = (uint32_t)(row * 128 + (((ks * 2 + lkA) ^ (row & 7)) * 16));
            LDSM_X4(qfh[ks][0], qfh[ks][1], qfh[ks][2], qfh[ks][3], qbh + off);
            LDSM_X4(qfl[ks][0], qfl[ks][1], qfl[ks][2], qfl[ks][3], qbl + off);
        }
    }

    const int rlo = q0 + wid * 16 + (lane >> 2);
    const int rhi = rlo + 8;
    const int cb = (lane & 3) * 2;
    const int lrB = (lane & 7) + ((lane >> 4) & 1) * 8;
    const int lkB = (lane >> 3) & 1;
    const int vlr = (lane & 7) + ((lane >> 3) & 1) * 8;
    const int vck = lane >> 4;

    float o[8][4];
    #pragma unroll
    for (int j = 0; j < 8; j++)
        #pragma unroll
        for (int r = 0; r < 4; r++) o[j][r] = 0.f;
    float m_lo = -1e30f, m_hi = -1e30f, l_lo = 0.f, l_hi = 0.f;

    const int ntiles = q0 / 64 + 1;
    for (int i = 0; i < ntiles; i++) {
        const int k0 = i * 64;
        const int buf = i & 1;
        if (i + 1 < ntiles) {
            load_kv((i + 1) & 1, k0 + 64);
            CP_COMMIT();
            CP_WAIT1();
        } else {
            CP_WAIT0();
        }
        __syncthreads();

        const int* smask = (const int*)(fs + FA_MSK + buf * 256);
        const uint32_t kbh = sbase + FA_BUF + buf * 32768u;
        const uint32_t kbl = kbh + 8192u;
        const uint32_t vbh = kbh + 16384u;
        const uint32_t vbl = kbh + 24576u;

        // ---- scores: S = Qh*Kh + Qh*Kl + Ql*Kh
        float s[8][4];
        #pragma unroll
        for (int j = 0; j < 8; j++)
            #pragma unroll
            for (int r = 0; r < 4; r++) s[j][r] = 0.f;

        #pragma unroll
        for (int jp = 0; jp < 4; jp++) {
            const int rowb = jp * 16 + lrB;
            #pragma unroll
            for (int ks = 0; ks < 4; ks++) {
                const uint32_t off = (uint32_t)(rowb * 128 + (((ks * 2 + lkB) ^ (rowb & 7)) * 16));
                uint32_t bh0, bh1, bh2, bh3, bl0, bl1, bl2, bl3;
                LDSM_X4(bh0, bh1, bh2, bh3, kbh + off);
                LDSM_X4(bl0, bl1, bl2, bl3, kbl + off);
                MMA_BF16(s[2 * jp],     qfh[ks], bh0, bh1);
                MMA_BF16(s[2 * jp],     qfh[ks], bl0, bl1);
                MMA_BF16(s[2 * jp],     qfl[ks], bh0, bh1);
                MMA_BF16(s[2 * jp + 1], qfh[ks], bh2, bh3);
                MMA_BF16(s[2 * jp + 1], qfh[ks], bl2, bl3);
                MMA_BF16(s[2 * jp + 1], qfl[ks], bh2, bh3);
            }
        }

        // ---- mask + online softmax
        float mloc_lo = -1e30f, mloc_hi = -1e30f;
        #pragma unroll
        for (int j = 0; j < 8; j++) {
            const int c0 = k0 + j * 8 + cb;
            const int c1 = c0 + 1;
            const bool mv0 = smask[j * 8 + cb] != 0;
            const bool mv1 = smask[j * 8 + cb + 1] != 0;
            s[j][0] = (mv0 && c0 <= rlo) ? s[j][0] * 0.125f : -1e30f;
            s[j][1] = (mv1 && c1 <= rlo) ? s[j][1] * 0.125f : -1e30f;
            s[j][2] = (mv0 && c0 <= rhi) ? s[j][2] * 0.125f : -1e30f;
            s[j][3] = (mv1 && c1 <= rhi) ? s[j][3] * 0.125f : -1e30f;
            mloc_lo = fmaxf(mloc_lo, fmaxf(s[j][0], s[j][1]));
            mloc_hi = fmaxf(mloc_hi, fmaxf(s[j][2], s[j][3]));
        }
        mloc_lo = fmaxf(mloc_lo, __shfl_xor_sync(0xFFFFFFFFu, mloc_lo, 1));
        mloc_lo = fmaxf(mloc_lo, __shfl_xor_sync(0xFFFFFFFFu, mloc_lo, 2));
        mloc_hi = fmaxf(mloc_hi, __shfl_xor_sync(0xFFFFFFFFu, mloc_hi, 1));
        mloc_hi = fmaxf(mloc_hi, __shfl_xor_sync(0xFFFFFFFFu, mloc_hi, 2));

        const float mnew_lo = fmaxf(m_lo, mloc_lo);
        const float mnew_hi = fmaxf(m_hi, mloc_hi);
        const float corr_lo = __expf(m_lo - mnew_lo);
        const float corr_hi = __expf(m_hi - mnew_hi);

        float ls_lo = 0.f, ls_hi = 0.f;
        #pragma unroll
        for (int j = 0; j < 8; j++) {
            s[j][0] = __expf(s[j][0] - mnew_lo);
            s[j][1] = __expf(s[j][1] - mnew_lo);
            s[j][2] = __expf(s[j][2] - mnew_hi);
            s[j][3] = __expf(s[j][3] - mnew_hi);
            ls_lo += s[j][0] + s[j][1];
            ls_hi += s[j][2] + s[j][3];
        }
        ls_lo += __shfl_xor_sync(0xFFFFFFFFu, ls_lo, 1);
        ls_lo += __shfl_xor_sync(0xFFFFFFFFu, ls_lo, 2);
        ls_hi += __shfl_xor_sync(0xFFFFFFFFu, ls_hi, 1);
        ls_hi += __shfl_xor_sync(0xFFFFFFFFu, ls_hi, 2);

        l_lo = l_lo * corr_lo + ls_lo;
        l_hi = l_hi * corr_hi + ls_hi;
        m_lo = mnew_lo; m_hi = mnew_hi;

        #pragma unroll
        for (int j = 0; j < 8; j++) {
            o[j][0] *= corr_lo; o[j][1] *= corr_lo;
            o[j][2] *= corr_hi; o[j][3] *= corr_hi;
        }

        // ---- PV: O += Ph*Vh + Pl*Vh + Ph*Vl
        #pragma unroll
        for (int t = 0; t < 4; t++) {
            uint32_t ah[4], al[4];
            bsplit2(s[2 * t][0],     s[2 * t][1],     ah[0], al[0]);
            bsplit2(s[2 * t][2],     s[2 * t][3],     ah[1], al[1]);
            bsplit2(s[2 * t + 1][0], s[2 * t + 1][1], ah[2], al[2]);
            bsplit2(s[2 * t + 1][2], s[2 * t + 1][3], ah[3], al[3]);
            const int vrow = t * 16 + vlr;
            #pragma unroll
            for (int ndp = 0; ndp < 4; ndp++) {
                const uint32_t off = (uint32_t)(vrow * 128 + (((ndp * 2 + vck) ^ (vrow & 7)) * 16));
                uint32_t vh0, vh1, vh2, vh3, vl0, vl1, vl2, vl3;
                LDSM_X4_T(vh0, vh1, vh2, vh3, vbh + off);
                LDSM_X4_T(vl0, vl1, vl2, vl3, vbl + off);
                MMA_BF16(o[2 * ndp],     ah, vh0, vh1);
                MMA_BF16(o[2 * ndp],     al, vh0, vh1);
                MMA_BF16(o[2 * ndp],     ah, vl0, vl1);
                MMA_BF16(o[2 * ndp + 1], ah, vh2, vh3);
                MMA_BF16(o[2 * ndp + 1], al, vh2, vh3);
                MMA_BF16(o[2 * ndp + 1], ah, vl2, vl3);
            }
        }
        __syncthreads();
    }

    // epilogue: normalize + tf32 pre-round (feeds the output GEMM)
    const float inv_lo = 1.f / l_lo;
    const float inv_hi = 1.f / l_hi;
    float* base_lo = O + ((size_t)(b * S_) + rlo) * DM + h * DK;
    float* base_hi = O + ((size_t)(b * S_) + rhi) * DM + h * DK;
    #pragma unroll
    for (int j = 0; j < 8; j++) {
        const int d = j * 8 + cb;
        *(float2*)(base_lo + d) = make_float2(tf32_rna(o[j][0] * inv_lo),
                                              tf32_rna(o[j][1] * inv_lo));
        *(float2*)(base_hi + d) = make_float2(tf32_rna(o[j][2] * inv_hi),
                                              tf32_rna(o[j][3] * inv_hi));
    }
}

// ---------------------------------------------------------------------------
// Launch
// ---------------------------------------------------------------------------
#define GEMM_SMEM 65536

extern "C" void kernel_launch(void* const* d_in, const int* in_sizes, int n_in,
                              void* d_out, int out_size)
{
    const float* x  = (const float*)d_in[0];
    const int*   am = (const int*)d_in[1];
    const float* wq = (const float*)d_in[2];
    const float* bq = (const float*)d_in[3];
    const float* wk = (const float*)d_in[4];
    const float* bk = (const float*)d_in[5];
    const float* wv = (const float*)d_in[6];
    const float* bv = (const float*)d_in[7];
    const float* wo = (const float*)d_in[8];
    const float* bo = (const float*)d_in[9];
    float* out = (float*)d_out;

    float *ap, *xc, *wc;
    __nv_bfloat16 *qh, *ql, *kh, *kl, *vh, *vl;
    cudaGetSymbolAddress((void**)&ap, g_att);
    cudaGetSymbolAddress((void**)&xc, g_xc);
    cudaGetSymbolAddress((void**)&wc, g_wc);
    cudaGetSymbolAddress((void**)&qh, g_qh);
    cudaGetSymbolAddress((void**)&ql, g_ql);
    cudaGetSymbolAddress((void**)&kh, g_kh);
    cudaGetSymbolAddress((void**)&kl, g_kl);
    cudaGetSymbolAddress((void**)&vh, g_vh);
    cudaGetSymbolAddress((void**)&vl, g_vl);
    float* woc = wc + 3 * DM * DM;

    cudaFuncSetAttribute(gemm_qkv_kernel,
                         cudaFuncAttributeMaxDynamicSharedMemorySize, GEMM_SMEM);
    cudaFuncSetAttribute(gemm_out_kernel,
                         cudaFuncAttributeMaxDynamicSharedMemorySize, GEMM_SMEM);
    cudaFuncSetAttribute(flash_attn_tc,
                         cudaFuncAttributeMaxDynamicSharedMemorySize, FA_SMEM);

    // fused tf32 pre-round: x + 4 weights, one launch
    tf32_round_all<<<1184, 256>>>((const float4*)x,
                                  (const float4*)wq, (const float4*)wk,
                                  (const float4*)wv, (const float4*)wo,
                                  (float4*)xc, (float4*)wc);

    dim3 qkvgrid(24, 32);
    gemm_qkv_kernel<<<qkvgrid, 256, GEMM_SMEM>>>(xc, wc, bq, bk, bv,
                                                 qh, ql, kh, kl, vh, vl);

    dim3 agrid(S_ / 64, H_, B_);        // (32, 16, 2)
    flash_attn_tc<<<agrid, 128, FA_SMEM>>>(qh, ql, kh, kl, vh, vl, am, ap);

    dim3 ogrid(DM / 128, MTOT / 128);   // (8, 32)
    gemm_out_kernel<<<ogrid, 256, GEMM_SMEM>>>(ap, woc, bo, out);
}